// round 2
// baseline (speedup 1.0000x reference)
#include <cuda_runtime.h>

#define BN 200
#define VN 64
#define HID 64
#define BV (BN*VN)
#define MN 73
#define NSW 10
#define EC 63
#define OUTC 210

// dynamic smem for layer kernel: 13632 floats
#define LAYER_SMEM (13632*4)

// ---------------- device scratch (allocation-free workaround) ----------------
__device__ float g_s[(long long)BN*VN*VN*HID];   // (B,V,V,H) edge state, ~210MB
__device__ float g_x[BV*HID];                    // node features (H)
__device__ float g_xi[BV*HID];
__device__ float g_xj[BV*HID];
__device__ float g_xu[BV*HID];
__device__ float g_xv[BV*HID];
__device__ float g_xg[BN*HID];
__device__ float g_vpar[BN*MN];
__device__ float g_vchi[BN*MN];
__device__ float g_conn[VN*VN];
__device__ float g_deginv[VN];
__device__ float g_embp[2*HID];
__device__ float g_Wp[VN*MN];
__device__ float g_Wc[VN*MN];
__device__ int   g_Sint[VN*VN];
__device__ int   g_swmask[VN*VN];

// ---------------- helpers ----------------
__device__ __forceinline__ float sigmoidf(float x){
    return __fdividef(1.0f, 1.0f + __expf(-x));
}
__device__ __forceinline__ float wsum(float v){
#pragma unroll
    for (int o = 16; o; o >>= 1) v += __shfl_xor_sync(0xffffffffu, v, o);
    return v;
}

// ---------------- setup: conn, deg_inv, S-int, embed@Ws, Dinv@Inc, switch mask ----------------
__global__ void setup_kernel(const float* __restrict__ A, const float* __restrict__ S,
                             const float* __restrict__ embed_s, const float* __restrict__ p0_Ws,
                             const float* __restrict__ Dinv,
                             const float* __restrict__ Incp, const float* __restrict__ Incc,
                             const int* __restrict__ edge_S)
{
    const int t = threadIdx.x; // 256 threads
    for (int i = t; i < VN*VN; i += 256){
        float a = A[i] + S[i];
        g_conn[i]   = fminf(fmaxf(a, 0.f), 1.f);
        g_Sint[i]   = (int)(S[i] + 0.5f);
        g_swmask[i] = 0;
    }
    __syncthreads();
    if (t < VN){
        float s = 0.f;
        for (int w = 0; w < VN; ++w) s += g_conn[t*VN + w];
        g_deginv[t] = __fdividef(1.0f, fmaxf(s, 1.0f));
    }
    if (t < 2*HID){
        int e = t >> 6, k = t & 63;
        float acc = 0.f;
        for (int h = 0; h < 32; ++h) acc = fmaf(embed_s[e*32 + h], p0_Ws[h*64 + k], acc);
        g_embp[t] = acc;
    }
    for (int i = t; i < VN*MN; i += 256){
        int n = i / MN;
        float d = Dinv[n*VN + n];
        g_Wp[i] = d * Incp[i];
        g_Wc[i] = d * Incc[i];
    }
    __syncthreads();
    if (t < NSW){
        int si = edge_S[t], sj = edge_S[NSW + t];
        g_swmask[si*VN + sj] = 1;
    }
}

// ---------------- node projections: xi=x@Wi, xj=x@Wj, xu=x@U, xv=x@V ----------------
template<int IN, bool FROMX>
__global__ void proj_kernel(const float* __restrict__ src,
                            const float* __restrict__ Wi, const float* __restrict__ Wj,
                            const float* __restrict__ Wu, const float* __restrict__ Wv)
{
    __shared__ float sx[64];
    const int bv = blockIdx.x, t = threadIdx.x; // 64 threads
    const float* s = FROMX ? (const float*)g_x : src;
    if (t < IN) sx[t] = s[(long)bv*IN + t];
    __syncthreads();
    const int mat = t >> 4;
    const int kq  = (t & 15) << 2;
    const float* W = (mat == 0) ? Wi : (mat == 1) ? Wj : (mat == 2) ? Wu : Wv;
    float4 acc = make_float4(0.f, 0.f, 0.f, 0.f);
#pragma unroll
    for (int h = 0; h < IN; ++h){
        const float xv = sx[h];
        const float4 wv = *(const float4*)(W + h*64 + kq);
        acc.x = fmaf(xv, wv.x, acc.x);
        acc.y = fmaf(xv, wv.y, acc.y);
        acc.z = fmaf(xv, wv.z, acc.z);
        acc.w = fmaf(xv, wv.w, acc.w);
    }
    float* dst = (mat == 0) ? g_xi : (mat == 1) ? g_xj : (mat == 2) ? g_xu : g_xv;
    *(float4*)(dst + (long)bv*64 + kq) = acc;
}

// ---------------- fused layer kernel ----------------
// MODE 0: first layer (s = embed lookup, no GEMM, x_out = h)
// MODE 1: mid layer  (GEMM, s_out = s+e, full s write, x_out = x+h)
// MODE 2: last layer (GEMM, s_out = s+e, s write only at switch pairs, x_out = x+h)
template<int MODE>
__global__ void layer_kernel(const float* __restrict__ Ws)
{
    extern __shared__ float sm[];
    float* sWs   = sm;           // 4096 pair-interleaved: [h][ (k&31)*2 + (k>>5) ]
    float* sXj   = sm + 4096;    // 4096 pair-interleaved per w row
    float* sXv   = sm + 8192;    // 4096
    float* sSrow = sm + 12288;   // 8*64 per-warp s row
    float* sRed  = sm + 12800;   // 8*64 msg reduction
    float* sEmb  = sm + 13312;   // 2*64
    float* sConn = sm + 13440;   // 64
    int*   sSid  = (int*)(sm + 13504); // 64
    int*   sMask = (int*)(sm + 13568); // 64

    const int bv = blockIdx.x;
    const int v  = bv & (VN - 1);
    const int b  = bv >> 6;
    const int t  = threadIdx.x;
    const int lane = t & 31;
    const int warp = t >> 5;

    const long xb = (long)b * (VN*HID);
    for (int i = t; i < VN*HID; i += 256){
        const int k  = i & 63;
        const int pi = (i & ~63) + ((k & 31) << 1) + (k >> 5);
        sXj[pi] = g_xj[xb + i];
        sXv[pi] = g_xv[xb + i];
        if (MODE != 0) sWs[pi] = Ws[i];
    }
    if (t < VN){
        sConn[t] = g_conn[v*VN + t];
        if (MODE == 0) sSid[t]  = g_Sint[v*VN + t];
        if (MODE == 2) sMask[t] = g_swmask[v*VN + t];
    }
    if (MODE == 0 && t < 2*HID) sEmb[t] = g_embp[t];
    __syncthreads();

    const long nb  = (long)bv * HID;
    const float xi0 = g_xi[nb + lane];
    const float xi1 = g_xi[nb + lane + 32];
    float msg0 = 0.f, msg1 = 0.f;

#pragma unroll 1
    for (int it = 0; it < 8; ++it){
        const int w = (it << 3) + warp;
        const float connw = sConn[w];
        const long srow = ((long)bv*VN + w) * HID;
        float e0, e1, sp0 = 0.f, sp1 = 0.f;
        if (MODE == 0){
            const int id = sSid[w];
            e0 = sEmb[id*HID + lane];
            e1 = sEmb[id*HID + lane + 32];
        } else {
            __syncwarp();
            const float2 sr = *(const float2*)(g_s + srow + lane*2);
            *(float2*)(sSrow + warp*64 + lane*2) = sr;
            __syncwarp();
            float a0 = 0.f, a1 = 0.f;
            const float4* s4 = (const float4*)(sSrow + warp*64);
#pragma unroll
            for (int hh = 0; hh < 16; ++hh){
                const float4 sv = s4[hh];
                float2 wv;
                wv = ((const float2*)(sWs + ((hh<<2)+0)*64))[lane];
                a0 = fmaf(sv.x, wv.x, a0); a1 = fmaf(sv.x, wv.y, a1);
                wv = ((const float2*)(sWs + ((hh<<2)+1)*64))[lane];
                a0 = fmaf(sv.y, wv.x, a0); a1 = fmaf(sv.y, wv.y, a1);
                wv = ((const float2*)(sWs + ((hh<<2)+2)*64))[lane];
                a0 = fmaf(sv.z, wv.x, a0); a1 = fmaf(sv.z, wv.y, a1);
                wv = ((const float2*)(sWs + ((hh<<2)+3)*64))[lane];
                a0 = fmaf(sv.w, wv.x, a0); a1 = fmaf(sv.w, wv.y, a1);
            }
            e0 = a0; e1 = a1;
            sp0 = sSrow[warp*64 + lane];
            sp1 = sSrow[warp*64 + lane + 32];
        }
        const float2 xjv = ((const float2*)(sXj + w*64))[lane];
        e0 += xi0 + xjv.x;
        e1 += xi1 + xjv.y;
        // LayerNorm over 64 values held 2-per-lane across the warp
        float s1 = e0 + e1;
        float s2 = fmaf(e0, e0, e1*e1);
        s1 = wsum(s1); s2 = wsum(s2);
        const float mean = s1 * 0.015625f;
        const float var  = fmaf(-mean, mean, s2 * 0.015625f);
        const float rstd = rsqrtf(var + 1e-5f);
        const float r0 = fmaxf((e0 - mean) * rstd, 0.f);
        const float r1 = fmaxf((e1 - mean) * rstd, 0.f);
        const float so0 = sp0 + r0;
        const float so1 = sp1 + r1;
        bool dow = true;
        if (MODE == 2) dow = (sMask[w] != 0);
        if (dow){
            g_s[srow + lane]      = so0;
            g_s[srow + 32 + lane] = so1;
        }
        const float g0 = connw * sigmoidf(so0);
        const float g1 = connw * sigmoidf(so1);
        const float2 xvv = ((const float2*)(sXv + w*64))[lane];
        msg0 = fmaf(g0, xvv.x, msg0);
        msg1 = fmaf(g1, xvv.y, msg1);
    }
    sRed[warp*64 + lane]      = msg0;
    sRed[warp*64 + lane + 32] = msg1;
    __syncthreads();
    if (warp == 0){
        float m0 = 0.f, m1 = 0.f;
#pragma unroll
        for (int wp = 0; wp < 8; ++wp){
            m0 += sRed[wp*64 + lane];
            m1 += sRed[wp*64 + lane + 32];
        }
        const float dinv = g_deginv[v];
        const float t0 = g_xu[nb + lane]      + m0 * dinv;
        const float t1 = g_xu[nb + lane + 32] + m1 * dinv;
        float s1 = t0 + t1;
        float s2 = fmaf(t0, t0, t1*t1);
        s1 = wsum(s1); s2 = wsum(s2);
        const float mean = s1 * 0.015625f;
        const float var  = fmaf(-mean, mean, s2 * 0.015625f);
        const float rstd = rsqrtf(var + 1e-5f);
        float h0 = fmaxf((t0 - mean) * rstd, 0.f);
        float h1 = fmaxf((t1 - mean) * rstd, 0.f);
        if (MODE != 0){
            h0 += g_x[nb + lane];
            h1 += g_x[nb + lane + 32];
        }
        g_x[nb + lane]      = h0;
        g_x[nb + lane + 32] = h1;
    }
}

// ---------------- graph feature ----------------
__global__ void xg_kernel()
{
    const int b = blockIdx.x, k = threadIdx.x;
    float a = 0.f;
    for (int v = 0; v < VN; ++v) a += g_x[((long)b*VN + v)*HID + k];
    g_xg[b*HID + k] = a;
}

// ---------------- switch head MLP (in=256 -> 256 -> 4) ----------------
__global__ void smlp_kernel(const float* __restrict__ W1, const float* __restrict__ W2,
                            const int* __restrict__ edge_S, float* __restrict__ out)
{
    __shared__ float sin[256];
    __shared__ float shid[256];
    const int blk = blockIdx.x;
    const int b = blk / NSW, e = blk % NSW;
    const int t = threadIdx.x; // 128
    const int si = edge_S[e], sj = edge_S[NSW + e];
    for (int i = t; i < 256; i += 128){
        const int seg = i >> 6, k = i & 63;
        float val;
        if      (seg == 0) val = g_s[(((long)b*VN + si)*VN + sj)*HID + k];
        else if (seg == 1) val = g_x[((long)b*VN + si)*HID + k];
        else if (seg == 2) val = g_x[((long)b*VN + sj)*HID + k];
        else               val = g_xg[b*HID + k];
        sin[i] = val;
    }
    __syncthreads();
    if (t < 64){
        float a0 = 0.f, a1 = 0.f, a2 = 0.f, a3 = 0.f;
        const int kq = t << 2;
        for (int h = 0; h < 256; ++h){
            const float xv = sin[h];
            const float4 wv = *(const float4*)(W1 + h*256 + kq);
            a0 = fmaf(xv, wv.x, a0); a1 = fmaf(xv, wv.y, a1);
            a2 = fmaf(xv, wv.z, a2); a3 = fmaf(xv, wv.w, a3);
        }
        shid[kq+0] = fmaxf(a0, 0.f); shid[kq+1] = fmaxf(a1, 0.f);
        shid[kq+2] = fmaxf(a2, 0.f); shid[kq+3] = fmaxf(a3, 0.f);
    }
    __syncthreads();
    const int j = t >> 5, lane = t & 31;
    float acc = 0.f;
#pragma unroll
    for (int i = 0; i < 8; ++i){
        const int h = lane + 32*i;
        acc = fmaf(shid[h], W2[h*4 + j], acc);
    }
    acc = wsum(acc);
    if (lane == 0){
        const float sg = sigmoidf(acc);
        if      (j == 0) out[b*OUTC + 2*MN + VN - NSW + e] = sg;        // graph_topo tail
        else if (j == 1) out[b*OUTC + EC + e] = sg - 0.5f;              // ps
        else if (j == 2) g_vpar[b*MN + EC + e] = fmaf(0.2f, sg, 0.9f);  // vs_p
        else             g_vchi[b*MN + EC + e] = fmaf(0.2f, sg, 0.9f);  // vs_c
    }
}

// ---------------- connection head MLP (in=192 -> 192 -> 3) ----------------
__global__ void cmlp_kernel(const float* __restrict__ W1, const float* __restrict__ W2,
                            const int* __restrict__ edge_A, float* __restrict__ out)
{
    __shared__ float sin[192];
    __shared__ float shid[192];
    const int blk = blockIdx.x;
    const int b = blk / EC, e = blk % EC;
    const int t = threadIdx.x; // 128
    const int ai = edge_A[e], aj = edge_A[EC + e];
    for (int i = t; i < 192; i += 128){
        const int seg = i >> 6, k = i & 63;
        float val;
        if      (seg == 0) val = g_x[((long)b*VN + ai)*HID + k];
        else if (seg == 1) val = g_x[((long)b*VN + aj)*HID + k];
        else               val = g_xg[b*HID + k];
        sin[i] = val;
    }
    __syncthreads();
    if (t < 48){
        float a0 = 0.f, a1 = 0.f, a2 = 0.f, a3 = 0.f;
        const int kq = t << 2;
        for (int h = 0; h < 192; ++h){
            const float xv = sin[h];
            const float4 wv = *(const float4*)(W1 + h*192 + kq);
            a0 = fmaf(xv, wv.x, a0); a1 = fmaf(xv, wv.y, a1);
            a2 = fmaf(xv, wv.z, a2); a3 = fmaf(xv, wv.w, a3);
        }
        shid[kq+0] = fmaxf(a0, 0.f); shid[kq+1] = fmaxf(a1, 0.f);
        shid[kq+2] = fmaxf(a2, 0.f); shid[kq+3] = fmaxf(a3, 0.f);
    }
    __syncthreads();
    if (t < 96){
        const int j = t >> 5, lane = t & 31;
        float acc = 0.f;
#pragma unroll
        for (int i = 0; i < 6; ++i){
            const int h = lane + 32*i;
            acc = fmaf(shid[h], W2[h*3 + j], acc);
        }
        acc = wsum(acc);
        if (lane == 0){
            const float sg = sigmoidf(acc);
            if      (j == 0) out[b*OUTC + e] = sg - 0.5f;               // pc
            else if (j == 1) g_vpar[b*MN + e] = fmaf(0.2f, sg, 0.9f);   // vc_p
            else             g_vchi[b*MN + e] = fmaf(0.2f, sg, 0.9f);   // vc_c
        }
    }
}

// ---------------- voltage scatter + constants ----------------
__global__ void vout_kernel(float* __restrict__ out)
{
    __shared__ float vp[MN], vc[MN];
    const int b = blockIdx.x, t = threadIdx.x; // 64
    for (int i = t; i < MN; i += 64){
        vp[i] = g_vpar[b*MN + i];
        vc[i] = g_vchi[b*MN + i];
    }
    __syncthreads();
    float acc = 0.f;
    for (int m = 0; m < MN; ++m){
        acc = fmaf(vp[m], g_Wp[t*MN + m], acc);
        acc = fmaf(vc[m], g_Wc[t*MN + m], acc);
    }
    out[b*OUTC + MN + t] = (t == 0) ? 1.0f : acc;   // v, with v[:,0]=1
    if (t < EC) out[b*OUTC + MN + VN + t] = 1.0f;   // graph_topo ones
}

// ---------------- launch ----------------
extern "C" void kernel_launch(void* const* d_in, const int* in_sizes, int n_in,
                              void* d_out, int out_size)
{
    const float* x       = (const float*)d_in[0];
    const float* A       = (const float*)d_in[1];
    const float* S       = (const float*)d_in[2];
    const float* embed_s = (const float*)d_in[3];
    const float* p0_Ws   = (const float*)d_in[4];
    const float* p0_Wi   = (const float*)d_in[5];
    const float* p0_Wj   = (const float*)d_in[6];
    const float* p0_U    = (const float*)d_in[7];
    const float* p0_V    = (const float*)d_in[8];
    const float* pl_Ws   = (const float*)d_in[9];
    const float* pl_Wi   = (const float*)d_in[10];
    const float* pl_Wj   = (const float*)d_in[11];
    const float* pl_U    = (const float*)d_in[12];
    const float* pl_V    = (const float*)d_in[13];
    const float* smlp_W1 = (const float*)d_in[14];
    const float* smlp_W2 = (const float*)d_in[15];
    const float* cmlp_W1 = (const float*)d_in[16];
    const float* cmlp_W2 = (const float*)d_in[17];
    const float* Dinv    = (const float*)d_in[18];
    const float* Incp    = (const float*)d_in[19];
    const float* Incc    = (const float*)d_in[20];
    const int*   edge_A  = (const int*)d_in[21];
    const int*   edge_S  = (const int*)d_in[22];
    float* out = (float*)d_out;

    cudaFuncSetAttribute(layer_kernel<0>, cudaFuncAttributeMaxDynamicSharedMemorySize, LAYER_SMEM);
    cudaFuncSetAttribute(layer_kernel<1>, cudaFuncAttributeMaxDynamicSharedMemorySize, LAYER_SMEM);
    cudaFuncSetAttribute(layer_kernel<2>, cudaFuncAttributeMaxDynamicSharedMemorySize, LAYER_SMEM);

    setup_kernel<<<1, 256>>>(A, S, embed_s, p0_Ws, Dinv, Incp, Incc, edge_S);

    // layer 0 (first=True): embed lookup replaces GEMM
    proj_kernel<32, false><<<BV, 64>>>(x, p0_Wi, p0_Wj, p0_U, p0_V);
    layer_kernel<0><<<BV, 256, LAYER_SMEM>>>(nullptr);

    // layer 1
    proj_kernel<64, true><<<BV, 64>>>(nullptr, pl_Wi, pl_Wj, pl_U, pl_V);
    layer_kernel<1><<<BV, 256, LAYER_SMEM>>>(pl_Ws);

    // layer 2 (last): s written only at switch pairs
    proj_kernel<64, true><<<BV, 64>>>(nullptr, pl_Wi + 4096, pl_Wj + 4096,
                                      pl_U + 4096, pl_V + 4096);
    layer_kernel<2><<<BV, 256, LAYER_SMEM>>>(pl_Ws + 4096);

    xg_kernel<<<BN, 64>>>();
    smlp_kernel<<<BN*NSW, 128>>>(smlp_W1, smlp_W2, edge_S, out);
    cmlp_kernel<<<BN*EC, 128>>>(cmlp_W1, cmlp_W2, edge_A, out);
    vout_kernel<<<BN, 64>>>(out);
}

// round 7
// speedup vs baseline: 1.6368x; 1.6368x over previous
#include <cuda_runtime.h>

#define BN 200
#define VN 64
#define HID 64
#define BV (BN*VN)
#define MN 73
#define NSW 10
#define EC 63
#define OUTC 210

// ---- layer kernel smem layout (floats) ----
// sS   [0, 16896)   : 4 s tiles, stride-65 rows (4x4160=16640) ; overlaid later as msgsm stride-66 (4x4224=16896)
// sWs  [16896,20992): 64x64 weights row-major
// sStat[20992,22016): 1024 stat exchange
// sEmb [22016,22144): 2x64 (mode0)
// sConn[22144,22400): 4x64
// sSid [22400,22656): 4x64 int (mode0)
// sMask[22656,22912): 4x64 int (mode2)
#define SM_SS    0
#define SM_WS    16896
#define SM_STAT  20992
#define SM_EMB   22016
#define SM_CONN  22144
#define SM_SID   22400
#define SM_MASK  22656
#define SM_TOT   22912
#define LAYER_SMEM (SM_TOT*4)

typedef unsigned long long ull;

// ---------------- device scratch ----------------
__device__ float g_s[(long long)BN*VN*VN*HID];   // (B,V,V,H) edge state
__device__ float g_x[BV*HID];
__device__ float g_xi[BV*HID];
__device__ float g_xj[BV*HID];
__device__ float g_xu[BV*HID];
__device__ float g_xv[BV*HID];
__device__ float g_xg[BN*HID];
__device__ float g_vpar[BN*MN];
__device__ float g_vchi[BN*MN];
__device__ float g_conn[VN*VN];
__device__ float g_deginv[VN];
__device__ float g_embp[2*HID];
__device__ float g_Wp[VN*MN];
__device__ float g_Wc[VN*MN];
__device__ int   g_Sint[VN*VN];
__device__ int   g_swmask[VN*VN];

// ---------------- f32x2 helpers ----------------
__device__ __forceinline__ ull fma2(ull a, ull b, ull c){
    ull d; asm("fma.rn.f32x2 %0, %1, %2, %3;" : "=l"(d) : "l"(a), "l"(b), "l"(c)); return d;
}
__device__ __forceinline__ ull add2(ull a, ull b){
    ull d; asm("add.rn.f32x2 %0, %1, %2;" : "=l"(d) : "l"(a), "l"(b)); return d;
}
__device__ __forceinline__ ull mul2(ull a, ull b){
    ull d; asm("mul.rn.f32x2 %0, %1, %2;" : "=l"(d) : "l"(a), "l"(b)); return d;
}
__device__ __forceinline__ ull pack2(float lo, float hi){
    ull d; asm("mov.b64 %0, {%1, %2};" : "=l"(d) : "f"(lo), "f"(hi)); return d;
}
__device__ __forceinline__ void unpack2(ull v, float& lo, float& hi){
    asm("mov.b64 {%0, %1}, %2;" : "=f"(lo), "=f"(hi) : "l"(v));
}
__device__ __forceinline__ float sigmoidf(float x){
    return __fdividef(1.0f, 1.0f + __expf(-x));
}
__device__ __forceinline__ float fast_sigmoid(float x){
    float t; asm("tanh.approx.f32 %0, %1;" : "=f"(t) : "f"(0.5f*x));
    return fmaf(0.5f, t, 0.5f);
}
__device__ __forceinline__ float wsum(float v){
#pragma unroll
    for (int o = 16; o; o >>= 1) v += __shfl_xor_sync(0xffffffffu, v, o);
    return v;
}

// ---------------- setup ----------------
__global__ void setup_kernel(const float* __restrict__ A, const float* __restrict__ S,
                             const float* __restrict__ embed_s, const float* __restrict__ p0_Ws,
                             const float* __restrict__ Dinv,
                             const float* __restrict__ Incp, const float* __restrict__ Incc,
                             const int* __restrict__ edge_S)
{
    const int t = threadIdx.x; // 256
    for (int i = t; i < VN*VN; i += 256){
        float a = A[i] + S[i];
        g_conn[i]   = fminf(fmaxf(a, 0.f), 1.f);
        g_Sint[i]   = (int)(S[i] + 0.5f);
        g_swmask[i] = 0;
    }
    __syncthreads();
    if (t < VN){
        float s = 0.f;
        for (int w = 0; w < VN; ++w) s += g_conn[t*VN + w];
        g_deginv[t] = __fdividef(1.0f, fmaxf(s, 1.0f));
    }
    if (t < 2*HID){
        int e = t >> 6, k = t & 63;
        float acc = 0.f;
        for (int h = 0; h < 32; ++h) acc = fmaf(embed_s[e*32 + h], p0_Ws[h*64 + k], acc);
        g_embp[t] = acc;
    }
    for (int i = t; i < VN*MN; i += 256){
        int n = i / MN;
        float d = Dinv[n*VN + n];
        g_Wp[i] = d * Incp[i];
        g_Wc[i] = d * Incc[i];
    }
    __syncthreads();
    if (t < NSW){
        int si = edge_S[t], sj = edge_S[NSW + t];
        g_swmask[si*VN + sj] = 1;
    }
}

// ---------------- node projections: 8 rows/block, f32x2 ----------------
template<int IN, bool FROMX>
__global__ void proj_kernel(const float* __restrict__ src,
                            const float* __restrict__ Wi, const float* __restrict__ Wj,
                            const float* __restrict__ Wu, const float* __restrict__ Wv)
{
    __shared__ float sxT[IN*8];  // [h][r]
    const int bv0 = blockIdx.x * 8;
    const int t = threadIdx.x;   // 256
    const float* s = FROMX ? (const float*)g_x : src;
    for (int i = t; i < 8*IN; i += 256){
        int r = i / IN, h = i % IN;
        sxT[h*8 + r] = s[(long)(bv0 + r)*IN + h];
    }
    __syncthreads();
    const int m = t >> 6, c = t & 63;
    const float* W = (m == 0) ? Wi : (m == 1) ? Wj : (m == 2) ? Wu : Wv;
    ull acc0 = 0, acc1 = 0, acc2 = 0, acc3 = 0;
#pragma unroll 8
    for (int h = 0; h < IN; ++h){
        const float wv = W[h*64 + c];
        const ull w2 = pack2(wv, wv);
        const ulonglong2 xa = *(const ulonglong2*)(sxT + h*8);
        const ulonglong2 xb = *(const ulonglong2*)(sxT + h*8 + 4);
        acc0 = fma2(xa.x, w2, acc0);
        acc1 = fma2(xa.y, w2, acc1);
        acc2 = fma2(xb.x, w2, acc2);
        acc3 = fma2(xb.y, w2, acc3);
    }
    float* dst = (m == 0) ? g_xi : (m == 1) ? g_xj : (m == 2) ? g_xu : g_xv;
    float a, b;
    unpack2(acc0, a, b); dst[(long)(bv0+0)*64 + c] = a; dst[(long)(bv0+1)*64 + c] = b;
    unpack2(acc1, a, b); dst[(long)(bv0+2)*64 + c] = a; dst[(long)(bv0+3)*64 + c] = b;
    unpack2(acc2, a, b); dst[(long)(bv0+4)*64 + c] = a; dst[(long)(bv0+5)*64 + c] = b;
    unpack2(acc3, a, b); dst[(long)(bv0+6)*64 + c] = a; dst[(long)(bv0+7)*64 + c] = b;
}

// ---------------- fused layer kernel ----------------
// block = 256 threads = 8 warps, handles 4 v's of one batch b.
// warp wpid: vpair = wpid>>2 (v local 2*vpair, 2*vpair+1), rh = (wpid>>1)&1, kh = wpid&1
// lane owns row w = rh*32+lane, cols [kh*32, kh*32+32), for both v's of its pair.
template<int MODE>
__global__ __launch_bounds__(256, 2) void layer_kernel(const float* __restrict__ Ws)
{
    extern __shared__ float sm[];
    float* sS    = sm + SM_SS;
    float* sWs   = sm + SM_WS;
    float* sStat = sm + SM_STAT;
    float* sEmb  = sm + SM_EMB;
    float* sConn = sm + SM_CONN;
    int*   sSid  = (int*)(sm + SM_SID);
    int*   sMask = (int*)(sm + SM_MASK);

    const int b     = blockIdx.x >> 4;
    const int vbase = (blockIdx.x & 15) << 2;
    const int t = threadIdx.x;
    const int wpid = t >> 5, lane = t & 31;

    // ---- stage ----
    if (MODE != 0){
        const float4* gs4 = (const float4*)(g_s + (((long)b*VN + vbase)*VN)*HID);
        for (int i = t; i < 4096; i += 256){
            const float4 f = gs4[i];
            const int v = i >> 10, rem = i & 1023;
            const int w = rem >> 4, h4 = (rem & 15) << 2;
            float* d = sS + v*4160 + w*65 + h4;
            d[0] = f.x; d[1] = f.y; d[2] = f.z; d[3] = f.w;
        }
        for (int i = t; i < 1024; i += 256)
            ((float4*)sWs)[i] = ((const float4*)Ws)[i];
    }
    if (t < 256){
        const int v = t >> 6, w = t & 63;
        sConn[t] = g_conn[(vbase + v)*VN + w];
        if (MODE == 0) sSid[t]  = g_Sint[(vbase + v)*VN + w];
        if (MODE == 2) sMask[t] = g_swmask[(vbase + v)*VN + w];
    }
    if (MODE == 0 && t < 128) sEmb[t] = g_embp[t];
    __syncthreads();

    const int vpair = wpid >> 2, rh = (wpid >> 1) & 1, kh = wpid & 1;
    const int vl0 = vpair*2, vl1 = vl0 + 1;
    const int w  = rh*32 + lane;
    const int cb = kh*32;

    ull accA[16], accB[16];

    if (MODE == 0){
        const int id0 = sSid[vl0*64 + w];
        const int id1 = sSid[vl1*64 + w];
        const ulonglong2* e0p = (const ulonglong2*)(sEmb + id0*64 + cb);
        const ulonglong2* e1p = (const ulonglong2*)(sEmb + id1*64 + cb);
#pragma unroll
        for (int q = 0; q < 8; ++q){
            ulonglong2 e0 = e0p[q], e1 = e1p[q];
            accA[2*q] = e0.x; accA[2*q+1] = e0.y;
            accB[2*q] = e1.x; accB[2*q+1] = e1.y;
        }
    } else {
#pragma unroll
        for (int q = 0; q < 16; ++q){ accA[q] = 0ull; accB[q] = 0ull; }
        const float* s0p = sS + vl0*4160 + w*65;
        const float* s1p = sS + vl1*4160 + w*65;
#pragma unroll 4
        for (int h = 0; h < 64; ++h){
            const float s0 = s0p[h], s1 = s1p[h];
            const ull s0d = pack2(s0, s0);
            const ull s1d = pack2(s1, s1);
            const ulonglong2* wp = (const ulonglong2*)(sWs + h*64 + cb);
#pragma unroll
            for (int q = 0; q < 8; ++q){
                const ulonglong2 wv = wp[q];
                accA[2*q]   = fma2(s0d, wv.x, accA[2*q]);
                accA[2*q+1] = fma2(s0d, wv.y, accA[2*q+1]);
                accB[2*q]   = fma2(s1d, wv.x, accB[2*q]);
                accB[2*q+1] = fma2(s1d, wv.y, accB[2*q+1]);
            }
        }
    }

    // ---- add xi + xj ----
    {
        const ulonglong2* xjp  = (const ulonglong2*)(g_xj + ((long)b*64 + w)*64 + cb);
        const ulonglong2* xi0p = (const ulonglong2*)(g_xi + ((long)b*64 + vbase + vl0)*64 + cb);
        const ulonglong2* xi1p = (const ulonglong2*)(g_xi + ((long)b*64 + vbase + vl1)*64 + cb);
#pragma unroll
        for (int q = 0; q < 8; ++q){
            const ulonglong2 xj = xjp[q], x0 = xi0p[q], x1 = xi1p[q];
            accA[2*q]   = add2(accA[2*q],   add2(x0.x, xj.x));
            accA[2*q+1] = add2(accA[2*q+1], add2(x0.y, xj.y));
            accB[2*q]   = add2(accB[2*q],   add2(x1.x, xj.x));
            accB[2*q+1] = add2(accB[2*q+1], add2(x1.y, xj.y));
        }
    }

    // ---- row stats (lane-local over 32 cols, combine with kh-peer warp) ----
    ull sA = 0, qA = 0, sB = 0, qB = 0;
#pragma unroll
    for (int q = 0; q < 16; ++q){
        sA = add2(sA, accA[q]); qA = fma2(accA[q], accA[q], qA);
        sB = add2(sB, accB[q]); qB = fma2(accB[q], accB[q], qB);
    }
    float lo, hi, sumA, sqA, sumB, sqB;
    unpack2(sA, lo, hi); sumA = lo + hi;
    unpack2(qA, lo, hi); sqA  = lo + hi;
    unpack2(sB, lo, hi); sumB = lo + hi;
    unpack2(qB, lo, hi); sqB  = lo + hi;
    sStat[((wpid*2 + 0)*2 + 0)*32 + lane] = sumA;
    sStat[((wpid*2 + 0)*2 + 1)*32 + lane] = sqA;
    sStat[((wpid*2 + 1)*2 + 0)*32 + lane] = sumB;
    sStat[((wpid*2 + 1)*2 + 1)*32 + lane] = sqB;
    __syncthreads();
    {
        const int peer = wpid ^ 1;
        sumA += sStat[((peer*2 + 0)*2 + 0)*32 + lane];
        sqA  += sStat[((peer*2 + 0)*2 + 1)*32 + lane];
        sumB += sStat[((peer*2 + 1)*2 + 0)*32 + lane];
        sqB  += sStat[((peer*2 + 1)*2 + 1)*32 + lane];
    }
    const float mA = sumA * 0.015625f;
    const float rA = rsqrtf(fmaf(-mA, mA, sqA * 0.015625f) + 1e-5f);
    const float mB = sumB * 0.015625f;
    const float rB = rsqrtf(fmaf(-mB, mB, sqB * 0.015625f) + 1e-5f);

    // ---- LN + relu + residual + store s + gate + msg product ----
    const ulonglong2* xvp = (const ulonglong2*)(g_xv + ((long)b*64 + w)*64 + cb);
    {
        const float connv = sConn[vl0*64 + w];
        const float* sp = sS + vl0*4160 + w*65 + cb;
        float* gout = g_s + ((((long)b*64 + vbase + vl0)*64 + w)*64) + cb;
        const bool dow = (MODE == 2) ? (sMask[vl0*64 + w] != 0) : true;
#pragma unroll
        for (int q2 = 0; q2 < 8; ++q2){
            float a0, a1, a2, a3;
            unpack2(accA[2*q2],   a0, a1);
            unpack2(accA[2*q2+1], a2, a3);
            a0 = fmaxf((a0 - mA)*rA, 0.f); a1 = fmaxf((a1 - mA)*rA, 0.f);
            a2 = fmaxf((a2 - mA)*rA, 0.f); a3 = fmaxf((a3 - mA)*rA, 0.f);
            if (MODE != 0){
                a0 += sp[4*q2+0]; a1 += sp[4*q2+1]; a2 += sp[4*q2+2]; a3 += sp[4*q2+3];
            }
            if (dow) *(float4*)(gout + 4*q2) = make_float4(a0, a1, a2, a3);
            const float g0 = connv * fast_sigmoid(a0);
            const float g1 = connv * fast_sigmoid(a1);
            const float g2 = connv * fast_sigmoid(a2);
            const float g3 = connv * fast_sigmoid(a3);
            const ulonglong2 xv2 = xvp[q2];
            accA[2*q2]   = mul2(pack2(g0, g1), xv2.x);
            accA[2*q2+1] = mul2(pack2(g2, g3), xv2.y);
        }
    }
    {
        const float connv = sConn[vl1*64 + w];
        const float* sp = sS + vl1*4160 + w*65 + cb;
        float* gout = g_s + ((((long)b*64 + vbase + vl1)*64 + w)*64) + cb;
        const bool dow = (MODE == 2) ? (sMask[vl1*64 + w] != 0) : true;
#pragma unroll
        for (int q2 = 0; q2 < 8; ++q2){
            float a0, a1, a2, a3;
            unpack2(accB[2*q2],   a0, a1);
            unpack2(accB[2*q2+1], a2, a3);
            a0 = fmaxf((a0 - mB)*rB, 0.f); a1 = fmaxf((a1 - mB)*rB, 0.f);
            a2 = fmaxf((a2 - mB)*rB, 0.f); a3 = fmaxf((a3 - mB)*rB, 0.f);
            if (MODE != 0){
                a0 += sp[4*q2+0]; a1 += sp[4*q2+1]; a2 += sp[4*q2+2]; a3 += sp[4*q2+3];
            }
            if (dow) *(float4*)(gout + 4*q2) = make_float4(a0, a1, a2, a3);
            const float g0 = connv * fast_sigmoid(a0);
            const float g1 = connv * fast_sigmoid(a1);
            const float g2 = connv * fast_sigmoid(a2);
            const float g3 = connv * fast_sigmoid(a3);
            const ulonglong2 xv2 = xvp[q2];
            accB[2*q2]   = mul2(pack2(g0, g1), xv2.x);
            accB[2*q2+1] = mul2(pack2(g2, g3), xv2.y);
        }
    }
    __syncthreads();  // everyone done reading sS; reuse as msg matrix (stride 66)

    {
        float* mp0 = sS + vl0*4224 + w*66 + cb;
        float* mp1 = sS + vl1*4224 + w*66 + cb;
#pragma unroll
        for (int q = 0; q < 16; ++q){
            *(ull*)(mp0 + 2*q) = accA[q];
            *(ull*)(mp1 + 2*q) = accB[q];
        }
    }
    __syncthreads();

    // ---- msg reduce + node update: warp = (v = wpid>>1, khalf = wpid&1) ----
    {
        const int vl  = wpid >> 1;
        const int col = (wpid & 1)*32 + lane;
        const float* mpv = sS + vl*4224 + col;
        float msg = 0.f;
#pragma unroll 8
        for (int ww = 0; ww < 64; ++ww) msg += mpv[ww*66];
        const int vg = vbase + vl;
        const long nidx = ((long)b*64 + vg)*64 + col;
        const float tval = g_xu[nidx] + msg * g_deginv[vg];
        const float s1 = wsum(tval);
        const float s2 = wsum(tval * tval);
        if (lane == 0){
            sStat[vl*4 + (wpid & 1)*2 + 0] = s1;
            sStat[vl*4 + (wpid & 1)*2 + 1] = s2;
        }
        __syncthreads();
        const float st = sStat[vl*4 + 0] + sStat[vl*4 + 2];
        const float qt = sStat[vl*4 + 1] + sStat[vl*4 + 3];
        const float mean = st * 0.015625f;
        const float rstd = rsqrtf(fmaf(-mean, mean, qt * 0.015625f) + 1e-5f);
        float h = fmaxf((tval - mean) * rstd, 0.f);
        if (MODE != 0) h += g_x[nidx];
        g_x[nidx] = h;
    }
}

// ---------------- graph feature ----------------
__global__ void xg_kernel()
{
    const int b = blockIdx.x, k = threadIdx.x;
    float a = 0.f;
    for (int v = 0; v < VN; ++v) a += g_x[((long)b*VN + v)*HID + k];
    g_xg[b*HID + k] = a;
}

// ---------------- switch head MLP (256 -> 256 -> 4) ----------------
__global__ void smlp_kernel(const float* __restrict__ W1, const float* __restrict__ W2,
                            const int* __restrict__ edge_S, float* __restrict__ out)
{
    __shared__ float sin[256];
    __shared__ float shid[256];
    const int blk = blockIdx.x;
    const int b = blk / NSW, e = blk % NSW;
    const int t = threadIdx.x; // 128
    const int si = edge_S[e], sj = edge_S[NSW + e];
    for (int i = t; i < 256; i += 128){
        const int seg = i >> 6, k = i & 63;
        float val;
        if      (seg == 0) val = g_s[(((long)b*VN + si)*VN + sj)*HID + k];
        else if (seg == 1) val = g_x[((long)b*VN + si)*HID + k];
        else if (seg == 2) val = g_x[((long)b*VN + sj)*HID + k];
        else               val = g_xg[b*HID + k];
        sin[i] = val;
    }
    __syncthreads();
    if (t < 64){
        float a0 = 0.f, a1 = 0.f, a2 = 0.f, a3 = 0.f;
        const int kq = t << 2;
        for (int h = 0; h < 256; ++h){
            const float xv = sin[h];
            const float4 wv = *(const float4*)(W1 + h*256 + kq);
            a0 = fmaf(xv, wv.x, a0); a1 = fmaf(xv, wv.y, a1);
            a2 = fmaf(xv, wv.z, a2); a3 = fmaf(xv, wv.w, a3);
        }
        shid[kq+0] = fmaxf(a0, 0.f); shid[kq+1] = fmaxf(a1, 0.f);
        shid[kq+2] = fmaxf(a2, 0.f); shid[kq+3] = fmaxf(a3, 0.f);
    }
    __syncthreads();
    const int j = t >> 5, lane = t & 31;
    float acc = 0.f;
#pragma unroll
    for (int i = 0; i < 8; ++i){
        const int h = lane + 32*i;
        acc = fmaf(shid[h], W2[h*4 + j], acc);
    }
    acc = wsum(acc);
    if (lane == 0){
        const float sg = sigmoidf(acc);
        if      (j == 0) out[b*OUTC + 2*MN + VN - NSW + e] = sg;
        else if (j == 1) out[b*OUTC + EC + e] = sg - 0.5f;
        else if (j == 2) g_vpar[b*MN + EC + e] = fmaf(0.2f, sg, 0.9f);
        else             g_vchi[b*MN + EC + e] = fmaf(0.2f, sg, 0.9f);
    }
}

// ---------------- connection head MLP (192 -> 192 -> 3) ----------------
__global__ void cmlp_kernel(const float* __restrict__ W1, const float* __restrict__ W2,
                            const int* __restrict__ edge_A, float* __restrict__ out)
{
    __shared__ float sin[192];
    __shared__ float shid[192];
    const int blk = blockIdx.x;
    const int b = blk / EC, e = blk % EC;
    const int t = threadIdx.x; // 128
    const int ai = edge_A[e], aj = edge_A[EC + e];
    for (int i = t; i < 192; i += 128){
        const int seg = i >> 6, k = i & 63;
        float val;
        if      (seg == 0) val = g_x[((long)b*VN + ai)*HID + k];
        else if (seg == 1) val = g_x[((long)b*VN + aj)*HID + k];
        else               val = g_xg[b*HID + k];
        sin[i] = val;
    }
    __syncthreads();
    if (t < 48){
        float a0 = 0.f, a1 = 0.f, a2 = 0.f, a3 = 0.f;
        const int kq = t << 2;
        for (int h = 0; h < 192; ++h){
            const float xv = sin[h];
            const float4 wv = *(const float4*)(W1 + h*192 + kq);
            a0 = fmaf(xv, wv.x, a0); a1 = fmaf(xv, wv.y, a1);
            a2 = fmaf(xv, wv.z, a2); a3 = fmaf(xv, wv.w, a3);
        }
        shid[kq+0] = fmaxf(a0, 0.f); shid[kq+1] = fmaxf(a1, 0.f);
        shid[kq+2] = fmaxf(a2, 0.f); shid[kq+3] = fmaxf(a3, 0.f);
    }
    __syncthreads();
    if (t < 96){
        const int j = t >> 5, lane = t & 31;
        float acc = 0.f;
#pragma unroll
        for (int i = 0; i < 6; ++i){
            const int h = lane + 32*i;
            acc = fmaf(shid[h], W2[h*3 + j], acc);
        }
        acc = wsum(acc);
        if (lane == 0){
            const float sg = sigmoidf(acc);
            if      (j == 0) out[b*OUTC + e] = sg - 0.5f;
            else if (j == 1) g_vpar[b*MN + e] = fmaf(0.2f, sg, 0.9f);
            else             g_vchi[b*MN + e] = fmaf(0.2f, sg, 0.9f);
        }
    }
}

// ---------------- voltage scatter + constants ----------------
__global__ void vout_kernel(float* __restrict__ out)
{
    __shared__ float vp[MN], vc[MN];
    const int b = blockIdx.x, t = threadIdx.x; // 64
    for (int i = t; i < MN; i += 64){
        vp[i] = g_vpar[b*MN + i];
        vc[i] = g_vchi[b*MN + i];
    }
    __syncthreads();
    float acc = 0.f;
    for (int m = 0; m < MN; ++m){
        acc = fmaf(vp[m], g_Wp[t*MN + m], acc);
        acc = fmaf(vc[m], g_Wc[t*MN + m], acc);
    }
    out[b*OUTC + MN + t] = (t == 0) ? 1.0f : acc;
    if (t < EC) out[b*OUTC + MN + VN + t] = 1.0f;
}

// ---------------- launch ----------------
extern "C" void kernel_launch(void* const* d_in, const int* in_sizes, int n_in,
                              void* d_out, int out_size)
{
    const float* x       = (const float*)d_in[0];
    const float* A       = (const float*)d_in[1];
    const float* S       = (const float*)d_in[2];
    const float* embed_s = (const float*)d_in[3];
    const float* p0_Ws   = (const float*)d_in[4];
    const float* p0_Wi   = (const float*)d_in[5];
    const float* p0_Wj   = (const float*)d_in[6];
    const float* p0_U    = (const float*)d_in[7];
    const float* p0_V    = (const float*)d_in[8];
    const float* pl_Ws   = (const float*)d_in[9];
    const float* pl_Wi   = (const float*)d_in[10];
    const float* pl_Wj   = (const float*)d_in[11];
    const float* pl_U    = (const float*)d_in[12];
    const float* pl_V    = (const float*)d_in[13];
    const float* smlp_W1 = (const float*)d_in[14];
    const float* smlp_W2 = (const float*)d_in[15];
    const float* cmlp_W1 = (const float*)d_in[16];
    const float* cmlp_W2 = (const float*)d_in[17];
    const float* Dinv    = (const float*)d_in[18];
    const float* Incp    = (const float*)d_in[19];
    const float* Incc    = (const float*)d_in[20];
    const int*   edge_A  = (const int*)d_in[21];
    const int*   edge_S  = (const int*)d_in[22];
    float* out = (float*)d_out;

    cudaFuncSetAttribute(layer_kernel<0>, cudaFuncAttributeMaxDynamicSharedMemorySize, LAYER_SMEM);
    cudaFuncSetAttribute(layer_kernel<1>, cudaFuncAttributeMaxDynamicSharedMemorySize, LAYER_SMEM);
    cudaFuncSetAttribute(layer_kernel<2>, cudaFuncAttributeMaxDynamicSharedMemorySize, LAYER_SMEM);

    setup_kernel<<<1, 256>>>(A, S, embed_s, p0_Ws, Dinv, Incp, Incc, edge_S);

    // layer 0 (first=True): embed lookup, no GEMM
    proj_kernel<32, false><<<BV/8, 256>>>(x, p0_Wi, p0_Wj, p0_U, p0_V);
    layer_kernel<0><<<BN*16, 256, LAYER_SMEM>>>(nullptr);

    // layer 1
    proj_kernel<64, true><<<BV/8, 256>>>(nullptr, pl_Wi, pl_Wj, pl_U, pl_V);
    layer_kernel<1><<<BN*16, 256, LAYER_SMEM>>>(pl_Ws);

    // layer 2 (last): s written only at switch pairs
    proj_kernel<64, true><<<BV/8, 256>>>(nullptr, pl_Wi + 4096, pl_Wj + 4096,
                                         pl_U + 4096, pl_V + 4096);
    layer_kernel<2><<<BN*16, 256, LAYER_SMEM>>>(pl_Ws + 4096);

    xg_kernel<<<BN, 64>>>();
    smlp_kernel<<<BN*NSW, 128>>>(smlp_W1, smlp_W2, edge_S, out);
    cmlp_kernel<<<BN*EC, 128>>>(cmlp_W1, cmlp_W2, edge_A, out);
    vout_kernel<<<BN, 64>>>(out);
}

// round 11
// speedup vs baseline: 2.0470x; 1.2507x over previous
#include <cuda_runtime.h>

#define BN 200
#define VN 64
#define HID 64
#define BV (BN*VN)
#define MN 73
#define NSW 10
#define EC 63
#define OUTC 210

// ---- layer kernel smem layout (floats) ----
// sS   [0,16896): GEMM tile [v][h][w] 4*4096=16384; overlay msg stride-66 rows 4*4224=16896
// sWs  [16896,20992): 64x64 weights row-major
// sStat[20992,22016)
// sEmb [22016,22144), sConn[22144,22400), sSid[22400,22656), sMask[22656,22912)
#define SM_WS    16896
#define SM_STAT  20992
#define SM_EMB   22016
#define SM_CONN  22144
#define SM_SID   22400
#define SM_MASK  22656
#define SM_TOT   22912
#define LAYER_SMEM (SM_TOT*4)

typedef unsigned long long ull;

// ---------------- device scratch ----------------
__device__ float g_s[(long long)BN*VN*VN*HID];   // h-major: [b][v][h][w]
__device__ float g_x[BV*HID];                    // [bv][k]
__device__ float g_xi[BV*HID];                   // [bv][k]
__device__ float g_xj[BV*HID];                   // transposed: [b][k][w]
__device__ float g_xu[BV*HID];                   // [bv][k]
__device__ float g_xv[BV*HID];                   // transposed: [b][k][w]
__device__ float g_xg[BN*HID];
__device__ float g_vpar[BN*MN];
__device__ float g_vchi[BN*MN];
__device__ float g_conn[VN*VN];
__device__ float g_deginv[VN];
__device__ float g_embp[2*HID];
__device__ float g_Wp[VN*MN];
__device__ float g_Wc[VN*MN];
__device__ int   g_Sint[VN*VN];
__device__ int   g_swmask[VN*VN];

// ---------------- f32x2 helpers ----------------
__device__ __forceinline__ ull fma2(ull a, ull b, ull c){
    ull d; asm("fma.rn.f32x2 %0, %1, %2, %3;" : "=l"(d) : "l"(a), "l"(b), "l"(c)); return d;
}
__device__ __forceinline__ ull add2(ull a, ull b){
    ull d; asm("add.rn.f32x2 %0, %1, %2;" : "=l"(d) : "l"(a), "l"(b)); return d;
}
__device__ __forceinline__ ull mul2(ull a, ull b){
    ull d; asm("mul.rn.f32x2 %0, %1, %2;" : "=l"(d) : "l"(a), "l"(b)); return d;
}
__device__ __forceinline__ ull pack2(float lo, float hi){
    ull d; asm("mov.b64 %0, {%1, %2};" : "=l"(d) : "f"(lo), "f"(hi)); return d;
}
__device__ __forceinline__ void unpack2(ull v, float& lo, float& hi){
    asm("mov.b64 {%0, %1}, %2;" : "=f"(lo), "=f"(hi) : "l"(v));
}
__device__ __forceinline__ float sigmoidf(float x){
    return __fdividef(1.0f, 1.0f + __expf(-x));
}
__device__ __forceinline__ float fast_sigmoid(float x){
    float t; asm("tanh.approx.f32 %0, %1;" : "=f"(t) : "f"(0.5f*x));
    return fmaf(0.5f, t, 0.5f);
}
__device__ __forceinline__ float wsum(float v){
#pragma unroll
    for (int o = 16; o; o >>= 1) v += __shfl_xor_sync(0xffffffffu, v, o);
    return v;
}

// ---------------- setup ----------------
__global__ void setup_kernel(const float* __restrict__ A, const float* __restrict__ S,
                             const float* __restrict__ embed_s, const float* __restrict__ p0_Ws,
                             const float* __restrict__ Dinv,
                             const float* __restrict__ Incp, const float* __restrict__ Incc,
                             const int* __restrict__ edge_S)
{
    const int t = threadIdx.x; // 256
    for (int i = t; i < VN*VN; i += 256){
        float a = A[i] + S[i];
        g_conn[i]   = fminf(fmaxf(a, 0.f), 1.f);
        g_Sint[i]   = (int)(S[i] + 0.5f);
        g_swmask[i] = 0;
    }
    __syncthreads();
    if (t < VN){
        float s = 0.f;
        for (int w = 0; w < VN; ++w) s += g_conn[t*VN + w];
        g_deginv[t] = __fdividef(1.0f, fmaxf(s, 1.0f));
    }
    if (t < 2*HID){
        int e = t >> 6, k = t & 63;
        float acc = 0.f;
        for (int h = 0; h < 32; ++h) acc = fmaf(embed_s[e*32 + h], p0_Ws[h*64 + k], acc);
        g_embp[t] = acc;
    }
    for (int i = t; i < VN*MN; i += 256){
        int n = i / MN;
        float d = Dinv[n*VN + n];
        g_Wp[i] = d * Incp[i];
        g_Wc[i] = d * Incc[i];
    }
    __syncthreads();
    if (t < NSW){
        int si = edge_S[t], sj = edge_S[NSW + t];
        g_swmask[si*VN + sj] = 1;
    }
}

// ---------------- node projections: 16 rows/block ----------------
// xi, xu stored [bv][k]; xj, xv stored transposed [b][k][w]
template<int IN, bool FROMX>
__global__ void proj_kernel(const float* __restrict__ src,
                            const float* __restrict__ Wi, const float* __restrict__ Wj,
                            const float* __restrict__ Wu, const float* __restrict__ Wv)
{
    __shared__ float sxT[IN*20];  // [h]*20 + r, 16B-aligned rows (80B stride)
    const int bv0 = blockIdx.x * 16;
    const int b   = bv0 >> 6;
    const int w0  = bv0 & 63;
    const int t = threadIdx.x;   // 256
    const float* s = FROMX ? (const float*)g_x : src;
    for (int i = t; i < 16*IN; i += 256){
        int r = i / IN, h = i - r*IN;
        sxT[h*20 + r] = s[(long)(bv0 + r)*IN + h];
    }
    __syncthreads();
    const int m = t >> 6, c = t & 63;
    const float* W = (m == 0) ? Wi : (m == 1) ? Wj : (m == 2) ? Wu : Wv;
    ull acc[8];
#pragma unroll
    for (int q = 0; q < 8; ++q) acc[q] = 0ull;
#pragma unroll 8
    for (int h = 0; h < IN; ++h){
        const float wv = W[h*64 + c];
        const ull w2 = pack2(wv, wv);
        const ulonglong2* xp = (const ulonglong2*)(sxT + h*20);
#pragma unroll
        for (int q2 = 0; q2 < 4; ++q2){
            const ulonglong2 xq = xp[q2];
            acc[2*q2]   = fma2(xq.x, w2, acc[2*q2]);
            acc[2*q2+1] = fma2(xq.y, w2, acc[2*q2+1]);
        }
    }
    float tmp[16];
#pragma unroll
    for (int q = 0; q < 8; ++q) unpack2(acc[q], tmp[2*q], tmp[2*q+1]);
    if (m == 0 || m == 2){
        float* dst = (m == 0) ? g_xi : g_xu;
#pragma unroll
        for (int r = 0; r < 16; ++r) dst[(long)(bv0 + r)*64 + c] = tmp[r];
    } else {
        float* dst = ((m == 1) ? g_xj : g_xv) + ((long)(b*64 + c))*64 + w0;
#pragma unroll
        for (int q = 0; q < 4; ++q)
            *(float4*)(dst + 4*q) = make_float4(tmp[4*q], tmp[4*q+1], tmp[4*q+2], tmp[4*q+3]);
    }
}

// ---------------- fused layer kernel ----------------
// block = 8 warps, 4 v's of one batch. warp: vpair = wpid>>2, rh=(wpid>>1)&1, kh=wpid&1.
// lane owns edge row w = rh*32+lane, cols [kh*32, kh*32+32), for both v's of its pair.
template<int MODE>
__global__ __launch_bounds__(256, 2) void layer_kernel(const float* __restrict__ Ws)
{
    extern __shared__ float sm[];
    float* sSg   = sm;            // [v][h][w]
    float* sMsg  = sm;            // overlay after epilogue, stride 66
    float* sWs   = sm + SM_WS;
    float* sStat = sm + SM_STAT;
    float* sEmb  = sm + SM_EMB;
    float* sConn = sm + SM_CONN;
    int*   sSid  = (int*)(sm + SM_SID);
    int*   sMask = (int*)(sm + SM_MASK);

    const int b     = blockIdx.x >> 4;
    const int vbase = (blockIdx.x & 15) << 2;
    const int t = threadIdx.x;
    const int wpid = t >> 5, lane = t & 31;

    // ---- stage (identity copy thanks to h-major layout) ----
    if (MODE != 0){
        const float4* gs4 = (const float4*)(g_s + ((long)(b*VN + vbase))*(VN*HID));
        float4* ss4 = (float4*)sSg;
        for (int i = t; i < 4096; i += 256) ss4[i] = gs4[i];
        for (int i = t; i < 1024; i += 256)
            ((float4*)sWs)[i] = ((const float4*)Ws)[i];
    }
    if (t < 256){
        const int v = t >> 6, w = t & 63;
        sConn[t] = g_conn[(vbase + v)*VN + w];
        if (MODE == 0) sSid[t]  = g_Sint[(vbase + v)*VN + w];
        if (MODE == 2) sMask[t] = g_swmask[(vbase + v)*VN + w];
    }
    if (MODE == 0 && t < 128) sEmb[t] = g_embp[t];
    __syncthreads();

    const int vpair = wpid >> 2, rh = (wpid >> 1) & 1, kh = wpid & 1;
    const int vl0 = vpair*2, vl1 = vl0 + 1;
    const int w  = rh*32 + lane;
    const int cb = kh*32;

    ull accA[16], accB[16];

    if (MODE == 0){
        const int id0 = sSid[vl0*64 + w];
        const int id1 = sSid[vl1*64 + w];
        const ulonglong2* e0p = (const ulonglong2*)(sEmb + id0*64 + cb);
        const ulonglong2* e1p = (const ulonglong2*)(sEmb + id1*64 + cb);
#pragma unroll
        for (int q = 0; q < 8; ++q){
            ulonglong2 e0 = e0p[q], e1 = e1p[q];
            accA[2*q] = e0.x; accA[2*q+1] = e0.y;
            accB[2*q] = e1.x; accB[2*q+1] = e1.y;
        }
    } else {
#pragma unroll
        for (int q = 0; q < 16; ++q){ accA[q] = 0ull; accB[q] = 0ull; }
        const float* s0p = sSg + vl0*4096 + w;
        const float* s1p = sSg + vl1*4096 + w;
#pragma unroll 4
        for (int h = 0; h < 64; ++h){
            const float s0 = s0p[h*64], s1 = s1p[h*64];
            const ull s0d = pack2(s0, s0);
            const ull s1d = pack2(s1, s1);
            const ulonglong2* wp = (const ulonglong2*)(sWs + h*64 + cb);
#pragma unroll
            for (int q = 0; q < 8; ++q){
                const ulonglong2 wv = wp[q];
                accA[2*q]   = fma2(s0d, wv.x, accA[2*q]);
                accA[2*q+1] = fma2(s0d, wv.y, accA[2*q+1]);
                accB[2*q]   = fma2(s1d, wv.x, accB[2*q]);
                accB[2*q+1] = fma2(s1d, wv.y, accB[2*q+1]);
            }
        }
    }

    // ---- add xi (row-major, broadcast) + xj (transposed, coalesced) ----
    {
        const ulonglong2* xi0p = (const ulonglong2*)(g_xi + ((long)b*64 + vbase + vl0)*64 + cb);
        const ulonglong2* xi1p = (const ulonglong2*)(g_xi + ((long)b*64 + vbase + vl1)*64 + cb);
        const float* xjT = g_xj + ((long)b*64)*64 + w;
#pragma unroll
        for (int q = 0; q < 8; ++q){
            const int k = cb + 4*q;
            const ull xjA = pack2(xjT[(k+0)*64], xjT[(k+1)*64]);
            const ull xjB = pack2(xjT[(k+2)*64], xjT[(k+3)*64]);
            const ulonglong2 x0 = xi0p[q], x1 = xi1p[q];
            accA[2*q]   = add2(accA[2*q],   add2(x0.x, xjA));
            accA[2*q+1] = add2(accA[2*q+1], add2(x0.y, xjB));
            accB[2*q]   = add2(accB[2*q],   add2(x1.x, xjA));
            accB[2*q+1] = add2(accB[2*q+1], add2(x1.y, xjB));
        }
    }

    // ---- row stats ----
    ull sA = 0, qA = 0, sB = 0, qB = 0;
#pragma unroll
    for (int q = 0; q < 16; ++q){
        sA = add2(sA, accA[q]); qA = fma2(accA[q], accA[q], qA);
        sB = add2(sB, accB[q]); qB = fma2(accB[q], accB[q], qB);
    }
    float lo, hi, sumA, sqA, sumB, sqB;
    unpack2(sA, lo, hi); sumA = lo + hi;
    unpack2(qA, lo, hi); sqA  = lo + hi;
    unpack2(sB, lo, hi); sumB = lo + hi;
    unpack2(qB, lo, hi); sqB  = lo + hi;
    sStat[((wpid*2 + 0)*2 + 0)*32 + lane] = sumA;
    sStat[((wpid*2 + 0)*2 + 1)*32 + lane] = sqA;
    sStat[((wpid*2 + 1)*2 + 0)*32 + lane] = sumB;
    sStat[((wpid*2 + 1)*2 + 1)*32 + lane] = sqB;
    __syncthreads();
    {
        const int peer = wpid ^ 1;
        sumA += sStat[((peer*2 + 0)*2 + 0)*32 + lane];
        sqA  += sStat[((peer*2 + 0)*2 + 1)*32 + lane];
        sumB += sStat[((peer*2 + 1)*2 + 0)*32 + lane];
        sqB  += sStat[((peer*2 + 1)*2 + 1)*32 + lane];
    }
    const float mA = sumA * 0.015625f;
    const float rA = rsqrtf(fmaf(-mA, mA, sqA * 0.015625f) + 1e-5f);
    const float mB = sumB * 0.015625f;
    const float rB = rsqrtf(fmaf(-mB, mB, sqB * 0.015625f) + 1e-5f);

    // ---- LN + relu + residual + coalesced s store + gate + msg product ----
    const float* xvT = g_xv + ((long)b*64)*64 + w;
    {
        const float connv = sConn[vl0*64 + w];
        const float* spT = sSg + vl0*4096 + w;
        float* gout = g_s + ((long)(b*64 + vbase + vl0))*4096 + w;
        const bool dow = (MODE == 2) ? (sMask[vl0*64 + w] != 0) : true;
#pragma unroll
        for (int q2 = 0; q2 < 8; ++q2){
            const int k0 = cb + 4*q2;
            float a0, a1, a2, a3;
            unpack2(accA[2*q2],   a0, a1);
            unpack2(accA[2*q2+1], a2, a3);
            a0 = fmaxf((a0 - mA)*rA, 0.f); a1 = fmaxf((a1 - mA)*rA, 0.f);
            a2 = fmaxf((a2 - mA)*rA, 0.f); a3 = fmaxf((a3 - mA)*rA, 0.f);
            if (MODE != 0){
                a0 += spT[(k0+0)*64]; a1 += spT[(k0+1)*64];
                a2 += spT[(k0+2)*64]; a3 += spT[(k0+3)*64];
            }
            if (dow){
                gout[(k0+0)*64] = a0; gout[(k0+1)*64] = a1;
                gout[(k0+2)*64] = a2; gout[(k0+3)*64] = a3;
            }
            const float g0 = connv * fast_sigmoid(a0);
            const float g1 = connv * fast_sigmoid(a1);
            const float g2 = connv * fast_sigmoid(a2);
            const float g3 = connv * fast_sigmoid(a3);
            accA[2*q2]   = mul2(pack2(g0, g1), pack2(xvT[(k0+0)*64], xvT[(k0+1)*64]));
            accA[2*q2+1] = mul2(pack2(g2, g3), pack2(xvT[(k0+2)*64], xvT[(k0+3)*64]));
        }
    }
    {
        const float connv = sConn[vl1*64 + w];
        const float* spT = sSg + vl1*4096 + w;
        float* gout = g_s + ((long)(b*64 + vbase + vl1))*4096 + w;
        const bool dow = (MODE == 2) ? (sMask[vl1*64 + w] != 0) : true;
#pragma unroll
        for (int q2 = 0; q2 < 8; ++q2){
            const int k0 = cb + 4*q2;
            float a0, a1, a2, a3;
            unpack2(accB[2*q2],   a0, a1);
            unpack2(accB[2*q2+1], a2, a3);
            a0 = fmaxf((a0 - mB)*rB, 0.f); a1 = fmaxf((a1 - mB)*rB, 0.f);
            a2 = fmaxf((a2 - mB)*rB, 0.f); a3 = fmaxf((a3 - mB)*rB, 0.f);
            if (MODE != 0){
                a0 += spT[(k0+0)*64]; a1 += spT[(k0+1)*64];
                a2 += spT[(k0+2)*64]; a3 += spT[(k0+3)*64];
            }
            if (dow){
                gout[(k0+0)*64] = a0; gout[(k0+1)*64] = a1;
                gout[(k0+2)*64] = a2; gout[(k0+3)*64] = a3;
            }
            const float g0 = connv * fast_sigmoid(a0);
            const float g1 = connv * fast_sigmoid(a1);
            const float g2 = connv * fast_sigmoid(a2);
            const float g3 = connv * fast_sigmoid(a3);
            accB[2*q2]   = mul2(pack2(g0, g1), pack2(xvT[(k0+0)*64], xvT[(k0+1)*64]));
            accB[2*q2+1] = mul2(pack2(g2, g3), pack2(xvT[(k0+2)*64], xvT[(k0+3)*64]));
        }
    }
    __syncthreads();  // done reading sSg; reuse region as msg matrix (stride 66)

    {
        float* mp0 = sMsg + vl0*4224 + w*66 + cb;
        float* mp1 = sMsg + vl1*4224 + w*66 + cb;
#pragma unroll
        for (int q = 0; q < 16; ++q){
            *(ull*)(mp0 + 2*q) = accA[q];
            *(ull*)(mp1 + 2*q) = accB[q];
        }
    }
    __syncthreads();

    // ---- msg reduce + node update ----
    {
        const int vl  = wpid >> 1;
        const int col = (wpid & 1)*32 + lane;
        const float* mpv = sMsg + vl*4224 + col;
        float msg = 0.f;
#pragma unroll 8
        for (int ww = 0; ww < 64; ++ww) msg += mpv[ww*66];
        const int vg = vbase + vl;
        const long nidx = ((long)b*64 + vg)*64 + col;
        const float tval = g_xu[nidx] + msg * g_deginv[vg];
        const float s1 = wsum(tval);
        const float s2 = wsum(tval * tval);
        if (lane == 0){
            sStat[vl*4 + (wpid & 1)*2 + 0] = s1;
            sStat[vl*4 + (wpid & 1)*2 + 1] = s2;
        }
        __syncthreads();
        const float st = sStat[vl*4 + 0] + sStat[vl*4 + 2];
        const float qt = sStat[vl*4 + 1] + sStat[vl*4 + 3];
        const float mean = st * 0.015625f;
        const float rstd = rsqrtf(fmaf(-mean, mean, qt * 0.015625f) + 1e-5f);
        float h = fmaxf((tval - mean) * rstd, 0.f);
        if (MODE != 0) h += g_x[nidx];
        g_x[nidx] = h;
    }
}

// ---------------- graph feature ----------------
__global__ void xg_kernel()
{
    const int b = blockIdx.x, k = threadIdx.x;
    float a = 0.f;
    for (int v = 0; v < VN; ++v) a += g_x[((long)b*VN + v)*HID + k];
    g_xg[b*HID + k] = a;
}

// ---------------- switch head: 32 rows/block GEMM (256 -> 256 -> 4) ----------------
__global__ void smlp_kernel(const float* __restrict__ W1, const float* __restrict__ W2,
                            const int* __restrict__ edge_S, float* __restrict__ out)
{
    __shared__ float sinT[256*36];   // [h]*36 + r (also reused as hidden)
    __shared__ float sW2[256*4];
    __shared__ int srow[3*32];       // b, si, sj per row
    const int t = threadIdx.x;       // 256
    const int blk = blockIdx.x;
    if (t < 32){
        const int gid = blk*32 + t;
        if (gid < BN*NSW){
            const int b = gid / NSW, e = gid - b*NSW;
            srow[t] = b; srow[32+t] = edge_S[e]; srow[64+t] = edge_S[NSW+e];
        } else srow[t] = -1;
    }
    for (int i = t; i < 1024; i += 256) sW2[i] = W2[i];
    __syncthreads();

    // gather inputs transposed: sinT[k*36 + r]
    const int seg = t >> 6, kk = t & 63;
    for (int r = 0; r < 32; ++r){
        const int b = srow[r];
        float val = 0.f;
        if (b >= 0){
            const int si = srow[32+r], sj = srow[64+r];
            if      (seg == 0) val = g_s[(((long)b*VN + si)*VN + kk)*HID + sj];
            else if (seg == 1) val = g_x[((long)b*VN + si)*HID + kk];
            else if (seg == 2) val = g_x[((long)b*VN + sj)*HID + kk];
            else               val = g_xg[b*HID + kk];
        }
        sinT[t*36 + r] = val;
    }
    __syncthreads();

    ull acc[16];
#pragma unroll
    for (int q = 0; q < 16; ++q) acc[q] = 0ull;
#pragma unroll 4
    for (int h = 0; h < 256; ++h){
        const float wv = W1[h*256 + t];
        const ull w2 = pack2(wv, wv);
        const ulonglong2* xp = (const ulonglong2*)(sinT + h*36);
#pragma unroll
        for (int q = 0; q < 8; ++q){
            const ulonglong2 xq = xp[q];
            acc[2*q]   = fma2(xq.x, w2, acc[2*q]);
            acc[2*q+1] = fma2(xq.y, w2, acc[2*q+1]);
        }
    }
    __syncthreads();  // done reading sinT; overwrite with relu(hidden)
    {
        float* hd = sinT + t*36;
#pragma unroll
        for (int q = 0; q < 16; ++q){
            float a, bq; unpack2(acc[q], a, bq);
            hd[2*q]   = fmaxf(a, 0.f);
            hd[2*q+1] = fmaxf(bq, 0.f);
        }
    }
    __syncthreads();

    if (t < 128){
        const int j = t & 3, r = t >> 2;
        const int gid = blk*32 + r;
        if (gid < BN*NSW){
            float a = 0.f;
#pragma unroll 8
            for (int h = 0; h < 256; ++h) a = fmaf(sinT[h*36 + r], sW2[h*4 + j], a);
            const float sg = sigmoidf(a);
            const int b = gid / NSW, e = gid - b*NSW;
            if      (j == 0) out[b*OUTC + 2*MN + VN - NSW + e] = sg;
            else if (j == 1) out[b*OUTC + EC + e] = sg - 0.5f;
            else if (j == 2) g_vpar[b*MN + EC + e] = fmaf(0.2f, sg, 0.9f);
            else             g_vchi[b*MN + EC + e] = fmaf(0.2f, sg, 0.9f);
        }
    }
}

// ---------------- connection head: 32 rows/block GEMM (192 -> 192 -> 3) ----------------
__global__ void cmlp_kernel(const float* __restrict__ W1, const float* __restrict__ W2,
                            const int* __restrict__ edge_A, float* __restrict__ out)
{
    __shared__ float sinT[192*36];
    __shared__ float sW2[192*3];
    __shared__ int srow[3*32];
    const int t = threadIdx.x;    // 192
    const int blk = blockIdx.x;
    if (t < 32){
        const int gid = blk*32 + t;
        if (gid < BN*EC){
            const int b = gid / EC, e = gid - b*EC;
            srow[t] = b; srow[32+t] = edge_A[e]; srow[64+t] = edge_A[EC+e];
        } else srow[t] = -1;
    }
    for (int i = t; i < 576; i += 192) sW2[i] = W2[i];
    __syncthreads();

    const int seg = t >> 6, kk = t & 63;
    for (int r = 0; r < 32; ++r){
        const int b = srow[r];
        float val = 0.f;
        if (b >= 0){
            const int ai = srow[32+r], aj = srow[64+r];
            if      (seg == 0) val = g_x[((long)b*VN + ai)*HID + kk];
            else if (seg == 1) val = g_x[((long)b*VN + aj)*HID + kk];
            else               val = g_xg[b*HID + kk];
        }
        sinT[t*36 + r] = val;
    }
    __syncthreads();

    ull acc[16];
#pragma unroll
    for (int q = 0; q < 16; ++q) acc[q] = 0ull;
#pragma unroll 4
    for (int h = 0; h < 192; ++h){
        const float wv = W1[h*192 + t];
        const ull w2 = pack2(wv, wv);
        const ulonglong2* xp = (const ulonglong2*)(sinT + h*36);
#pragma unroll
        for (int q = 0; q < 8; ++q){
            const ulonglong2 xq = xp[q];
            acc[2*q]   = fma2(xq.x, w2, acc[2*q]);
            acc[2*q+1] = fma2(xq.y, w2, acc[2*q+1]);
        }
    }
    __syncthreads();
    {
        float* hd = sinT + t*36;
#pragma unroll
        for (int q = 0; q < 16; ++q){
            float a, bq; unpack2(acc[q], a, bq);
            hd[2*q]   = fmaxf(a, 0.f);
            hd[2*q+1] = fmaxf(bq, 0.f);
        }
    }
    __syncthreads();

    if (t < 96){
        const int j = t % 3, r = t / 3;
        const int gid = blk*32 + r;
        if (gid < BN*EC){
            float a = 0.f;
#pragma unroll 8
            for (int h = 0; h < 192; ++h) a = fmaf(sinT[h*36 + r], sW2[h*3 + j], a);
            const float sg = sigmoidf(a);
            const int b = gid / EC, e = gid - b*EC;
            if      (j == 0) out[b*OUTC + e] = sg - 0.5f;
            else if (j == 1) g_vpar[b*MN + e] = fmaf(0.2f, sg, 0.9f);
            else             g_vchi[b*MN + e] = fmaf(0.2f, sg, 0.9f);
        }
    }
}

// ---------------- voltage scatter + constants ----------------
__global__ void vout_kernel(float* __restrict__ out)
{
    __shared__ float vp[MN], vc[MN];
    const int b = blockIdx.x, t = threadIdx.x; // 64
    for (int i = t; i < MN; i += 64){
        vp[i] = g_vpar[b*MN + i];
        vc[i] = g_vchi[b*MN + i];
    }
    __syncthreads();
    float acc = 0.f;
    for (int m = 0; m < MN; ++m){
        acc = fmaf(vp[m], g_Wp[t*MN + m], acc);
        acc = fmaf(vc[m], g_Wc[t*MN + m], acc);
    }
    out[b*OUTC + MN + t] = (t == 0) ? 1.0f : acc;
    if (t < EC) out[b*OUTC + MN + VN + t] = 1.0f;
}

// ---------------- launch ----------------
extern "C" void kernel_launch(void* const* d_in, const int* in_sizes, int n_in,
                              void* d_out, int out_size)
{
    const float* x       = (const float*)d_in[0];
    const float* A       = (const float*)d_in[1];
    const float* S       = (const float*)d_in[2];
    const float* embed_s = (const float*)d_in[3];
    const float* p0_Ws   = (const float*)d_in[4];
    const float* p0_Wi   = (const float*)d_in[5];
    const float* p0_Wj   = (const float*)d_in[6];
    const float* p0_U    = (const float*)d_in[7];
    const float* p0_V    = (const float*)d_in[8];
    const float* pl_Ws   = (const float*)d_in[9];
    const float* pl_Wi   = (const float*)d_in[10];
    const float* pl_Wj   = (const float*)d_in[11];
    const float* pl_U    = (const float*)d_in[12];
    const float* pl_V    = (const float*)d_in[13];
    const float* smlp_W1 = (const float*)d_in[14];
    const float* smlp_W2 = (const float*)d_in[15];
    const float* cmlp_W1 = (const float*)d_in[16];
    const float* cmlp_W2 = (const float*)d_in[17];
    const float* Dinv    = (const float*)d_in[18];
    const float* Incp    = (const float*)d_in[19];
    const float* Incc    = (const float*)d_in[20];
    const int*   edge_A  = (const int*)d_in[21];
    const int*   edge_S  = (const int*)d_in[22];
    float* out = (float*)d_out;

    cudaFuncSetAttribute(layer_kernel<0>, cudaFuncAttributeMaxDynamicSharedMemorySize, LAYER_SMEM);
    cudaFuncSetAttribute(layer_kernel<1>, cudaFuncAttributeMaxDynamicSharedMemorySize, LAYER_SMEM);
    cudaFuncSetAttribute(layer_kernel<2>, cudaFuncAttributeMaxDynamicSharedMemorySize, LAYER_SMEM);

    setup_kernel<<<1, 256>>>(A, S, embed_s, p0_Ws, Dinv, Incp, Incc, edge_S);

    // layer 0 (first=True): embed lookup, no GEMM
    proj_kernel<32, false><<<BV/16, 256>>>(x, p0_Wi, p0_Wj, p0_U, p0_V);
    layer_kernel<0><<<BN*16, 256, LAYER_SMEM>>>(nullptr);

    // layer 1
    proj_kernel<64, true><<<BV/16, 256>>>(nullptr, pl_Wi, pl_Wj, pl_U, pl_V);
    layer_kernel<1><<<BN*16, 256, LAYER_SMEM>>>(pl_Ws);

    // layer 2 (last): s written only at switch pairs
    proj_kernel<64, true><<<BV/16, 256>>>(nullptr, pl_Wi + 4096, pl_Wj + 4096,
                                          pl_U + 4096, pl_V + 4096);
    layer_kernel<2><<<BN*16, 256, LAYER_SMEM>>>(pl_Ws + 4096);

    xg_kernel<<<BN, 64>>>();
    smlp_kernel<<<(BN*NSW + 31)/32, 256>>>(smlp_W1, smlp_W2, edge_S, out);
    cmlp_kernel<<<(BN*EC + 31)/32, 192>>>(cmlp_W1, cmlp_W2, edge_A, out);
    vout_kernel<<<BN, 64>>>(out);
}

// round 12
// speedup vs baseline: 2.0998x; 1.0258x over previous
#include <cuda_runtime.h>

#define BN 200
#define VN 64
#define HID 64
#define BV (BN*VN)
#define MN 73
#define NSW 10
#define EC 63
#define OUTC 210

// ---- layer kernel smem layout (floats) ----
#define SM_WS    16896
#define SM_STAT  20992
#define SM_EMB   22016
#define SM_CONN  22144
#define SM_SID   22400
#define SM_MASK  22656
#define SM_TOT   22912
#define LAYER_SMEM (SM_TOT*4)

typedef unsigned long long ull;

// ---------------- device scratch ----------------
__device__ float g_s[(long long)BN*VN*VN*HID];   // h-major [b][v][h][w]; written by layer1, read by layer2 only
__device__ float g_sw[BN*NSW*HID];               // compact switch-edge s2 rows
__device__ float g_x[BV*HID];                    // [bv][k]
__device__ float g_xi0[BV*HID];                  // layer0 xi, kept for layer1 recompute
__device__ float g_xj0[BV*HID];                  // layer0 xj transposed [b][k][w], kept
__device__ float g_xi[BV*HID];
__device__ float g_xj[BV*HID];                   // transposed [b][k][w]
__device__ float g_xu[BV*HID];
__device__ float g_xv[BV*HID];                   // transposed [b][k][w]
__device__ float g_xg[BN*HID];
__device__ float g_vpar[BN*MN];
__device__ float g_vchi[BN*MN];
__device__ float g_conn[VN*VN];
__device__ float g_deginv[VN];
__device__ float g_embp[2*HID];
__device__ float g_Wp[VN*MN];
__device__ float g_Wc[VN*MN];
__device__ int   g_Sint[VN*VN];
__device__ int   g_swidx[VN*VN];                 // (v,w) -> switch index or -1

// ---------------- f32x2 helpers ----------------
__device__ __forceinline__ ull fma2(ull a, ull b, ull c){
    ull d; asm("fma.rn.f32x2 %0, %1, %2, %3;" : "=l"(d) : "l"(a), "l"(b), "l"(c)); return d;
}
__device__ __forceinline__ ull add2(ull a, ull b){
    ull d; asm("add.rn.f32x2 %0, %1, %2;" : "=l"(d) : "l"(a), "l"(b)); return d;
}
__device__ __forceinline__ ull mul2(ull a, ull b){
    ull d; asm("mul.rn.f32x2 %0, %1, %2;" : "=l"(d) : "l"(a), "l"(b)); return d;
}
__device__ __forceinline__ ull pack2(float lo, float hi){
    ull d; asm("mov.b64 %0, {%1, %2};" : "=l"(d) : "f"(lo), "f"(hi)); return d;
}
__device__ __forceinline__ void unpack2(ull v, float& lo, float& hi){
    asm("mov.b64 {%0, %1}, %2;" : "=f"(lo), "=f"(hi) : "l"(v));
}
__device__ __forceinline__ float sigmoidf(float x){
    return __fdividef(1.0f, 1.0f + __expf(-x));
}
__device__ __forceinline__ float fast_sigmoid(float x){
    float t; asm("tanh.approx.f32 %0, %1;" : "=f"(t) : "f"(0.5f*x));
    return fmaf(0.5f, t, 0.5f);
}
__device__ __forceinline__ float wsum(float v){
#pragma unroll
    for (int o = 16; o; o >>= 1) v += __shfl_xor_sync(0xffffffffu, v, o);
    return v;
}

// ---------------- setup ----------------
__global__ void setup_kernel(const float* __restrict__ A, const float* __restrict__ S,
                             const float* __restrict__ embed_s, const float* __restrict__ p0_Ws,
                             const float* __restrict__ Dinv,
                             const float* __restrict__ Incp, const float* __restrict__ Incc,
                             const int* __restrict__ edge_S)
{
    const int t = threadIdx.x; // 256
    for (int i = t; i < VN*VN; i += 256){
        float a = A[i] + S[i];
        g_conn[i]  = fminf(fmaxf(a, 0.f), 1.f);
        g_Sint[i]  = (int)(S[i] + 0.5f);
        g_swidx[i] = -1;
    }
    __syncthreads();
    if (t < VN){
        float s = 0.f;
        for (int w = 0; w < VN; ++w) s += g_conn[t*VN + w];
        g_deginv[t] = __fdividef(1.0f, fmaxf(s, 1.0f));
    }
    if (t < 2*HID){
        int e = t >> 6, k = t & 63;
        float acc = 0.f;
        for (int h = 0; h < 32; ++h) acc = fmaf(embed_s[e*32 + h], p0_Ws[h*64 + k], acc);
        g_embp[t] = acc;
    }
    for (int i = t; i < VN*MN; i += 256){
        int n = i / MN;
        float d = Dinv[n*VN + n];
        g_Wp[i] = d * Incp[i];
        g_Wc[i] = d * Incc[i];
    }
    __syncthreads();
    if (t < NSW){
        int si = edge_S[t], sj = edge_S[NSW + t];
        g_swidx[si*VN + sj] = t;
    }
}

// ---------------- node projections: 32 rows/block ----------------
// SLOT 0 -> (g_xi0, g_xj0, g_xu, g_xv); SLOT 1 -> (g_xi, g_xj, g_xu, g_xv)
template<int IN, bool FROMX, int SLOT>
__global__ void proj_kernel(const float* __restrict__ src,
                            const float* __restrict__ Wi, const float* __restrict__ Wj,
                            const float* __restrict__ Wu, const float* __restrict__ Wv)
{
    __shared__ float sxT[IN*36];  // [h]*36 + r (144B stride, 16B aligned)
    const int bv0 = blockIdx.x * 32;
    const int b   = bv0 >> 6;
    const int w0  = bv0 & 63;
    const int t = threadIdx.x;   // 256
    const float* s = FROMX ? (const float*)g_x : src;
    for (int i = t; i < 32*IN; i += 256){
        int r = i / IN, h = i - r*IN;
        sxT[h*36 + r] = s[(long)(bv0 + r)*IN + h];
    }
    __syncthreads();
    const int m = t >> 6, c = t & 63;
    const float* W = (m == 0) ? Wi : (m == 1) ? Wj : (m == 2) ? Wu : Wv;
    ull acc[16];
#pragma unroll
    for (int q = 0; q < 16; ++q) acc[q] = 0ull;
#pragma unroll 4
    for (int h = 0; h < IN; ++h){
        const float wv = W[h*64 + c];
        const ull w2 = pack2(wv, wv);
        const ulonglong2* xp = (const ulonglong2*)(sxT + h*36);
#pragma unroll
        for (int q2 = 0; q2 < 8; ++q2){
            const ulonglong2 xq = xp[q2];
            acc[2*q2]   = fma2(xq.x, w2, acc[2*q2]);
            acc[2*q2+1] = fma2(xq.y, w2, acc[2*q2+1]);
        }
    }
    float tmp[32];
#pragma unroll
    for (int q = 0; q < 16; ++q) unpack2(acc[q], tmp[2*q], tmp[2*q+1]);
    if (m == 0 || m == 2){
        float* dst = (m == 0) ? (SLOT == 0 ? g_xi0 : g_xi) : g_xu;
#pragma unroll
        for (int r = 0; r < 32; ++r) dst[(long)(bv0 + r)*64 + c] = tmp[r];
    } else {
        float* base = (m == 1) ? (SLOT == 0 ? g_xj0 : g_xj) : g_xv;
        float* dst = base + ((long)(b*64 + c))*64 + w0;
#pragma unroll
        for (int q = 0; q < 8; ++q)
            *(float4*)(dst + 4*q) = make_float4(tmp[4*q], tmp[4*q+1], tmp[4*q+2], tmp[4*q+3]);
    }
}

// ---------------- fused layer kernel ----------------
// MODE 0: first layer — embp lookup, NO s store
// MODE 1: mid layer  — recompute s0 in smem, GEMM, s1 = s0+e1 full store
// MODE 2: last layer — load s1, GEMM, compact switch-edge store to g_sw
template<int MODE>
__global__ __launch_bounds__(256, 2) void layer_kernel(const float* __restrict__ Ws)
{
    extern __shared__ float sm[];
    float* sSg   = sm;            // [v][h][w]
    float* sMsg  = sm;            // overlay after epilogue, stride 66
    float* sWs   = sm + SM_WS;
    float* sStat = sm + SM_STAT;
    float* sEmb  = sm + SM_EMB;
    float* sConn = sm + SM_CONN;
    int*   sSid  = (int*)(sm + SM_SID);
    int*   sIdx  = (int*)(sm + SM_MASK);

    const int b     = blockIdx.x >> 4;
    const int vbase = (blockIdx.x & 15) << 2;
    const int t = threadIdx.x;
    const int wpid = t >> 5, lane = t & 31;

    // ---- stage ----
    if (MODE == 2){
        const float4* gs4 = (const float4*)(g_s + ((long)(b*VN + vbase))*(VN*HID));
        float4* ss4 = (float4*)sSg;
        for (int i = t; i < 4096; i += 256) ss4[i] = gs4[i];
    }
    if (MODE != 0){
        for (int i = t; i < 1024; i += 256)
            ((float4*)sWs)[i] = ((const float4*)Ws)[i];
    }
    if (t < 256){
        const int v = t >> 6, w = t & 63;
        sConn[t] = g_conn[(vbase + v)*VN + w];
        if (MODE == 0) sSid[t] = g_Sint[(vbase + v)*VN + w];
        if (MODE == 2) sIdx[t] = g_swidx[(vbase + v)*VN + w];
    }
    if (MODE != 2 && t < 128) sEmb[t] = g_embp[t];
    __syncthreads();

    if (MODE == 1){
        // recompute s0 = relu(LN(embp[sid] + xi0 + xj0)) into sSg, thread-local LN
        const int v = t >> 6, w = t & 63;
        const int sid = g_Sint[(vbase + v)*VN + w];
        const float* emb = sEmb + sid*64;
        const float* xi0 = g_xi0 + ((long)b*64 + vbase + v)*64;
        const float* xj0 = g_xj0 + ((long)b*64)*64 + w;
        float* scol = sSg + v*4096 + w;
        float s1 = 0.f, s2 = 0.f;
#pragma unroll 4
        for (int h = 0; h < 64; ++h){
            const float val = emb[h] + xi0[h] + xj0[h*64];
            scol[h*64] = val;
            s1 += val; s2 = fmaf(val, val, s2);
        }
        const float mean = s1 * 0.015625f;
        const float rstd = rsqrtf(fmaf(-mean, mean, s2 * 0.015625f) + 1e-5f);
#pragma unroll 4
        for (int h = 0; h < 64; ++h)
            scol[h*64] = fmaxf((scol[h*64] - mean) * rstd, 0.f);
        __syncthreads();
    }

    const int vpair = wpid >> 2, rh = (wpid >> 1) & 1, kh = wpid & 1;
    const int vl0 = vpair*2, vl1 = vl0 + 1;
    const int w  = rh*32 + lane;
    const int cb = kh*32;

    ull accA[16], accB[16];

    if (MODE == 0){
        const int id0 = sSid[vl0*64 + w];
        const int id1 = sSid[vl1*64 + w];
        const ulonglong2* e0p = (const ulonglong2*)(sEmb + id0*64 + cb);
        const ulonglong2* e1p = (const ulonglong2*)(sEmb + id1*64 + cb);
#pragma unroll
        for (int q = 0; q < 8; ++q){
            ulonglong2 e0 = e0p[q], e1 = e1p[q];
            accA[2*q] = e0.x; accA[2*q+1] = e0.y;
            accB[2*q] = e1.x; accB[2*q+1] = e1.y;
        }
    } else {
#pragma unroll
        for (int q = 0; q < 16; ++q){ accA[q] = 0ull; accB[q] = 0ull; }
        const float* s0p = sSg + vl0*4096 + w;
        const float* s1p = sSg + vl1*4096 + w;
#pragma unroll 4
        for (int h = 0; h < 64; ++h){
            const float s0 = s0p[h*64], s1 = s1p[h*64];
            const ull s0d = pack2(s0, s0);
            const ull s1d = pack2(s1, s1);
            const ulonglong2* wp = (const ulonglong2*)(sWs + h*64 + cb);
#pragma unroll
            for (int q = 0; q < 8; ++q){
                const ulonglong2 wv = wp[q];
                accA[2*q]   = fma2(s0d, wv.x, accA[2*q]);
                accA[2*q+1] = fma2(s0d, wv.y, accA[2*q+1]);
                accB[2*q]   = fma2(s1d, wv.x, accB[2*q]);
                accB[2*q+1] = fma2(s1d, wv.y, accB[2*q+1]);
            }
        }
    }

    // ---- add xi (broadcast) + xj (transposed, coalesced) ----
    {
        const float* xiBuf = (MODE == 0) ? g_xi0 : g_xi;
        const float* xjBuf = (MODE == 0) ? g_xj0 : g_xj;
        const ulonglong2* xi0p = (const ulonglong2*)(xiBuf + ((long)b*64 + vbase + vl0)*64 + cb);
        const ulonglong2* xi1p = (const ulonglong2*)(xiBuf + ((long)b*64 + vbase + vl1)*64 + cb);
        const float* xjT = xjBuf + ((long)b*64)*64 + w;
#pragma unroll
        for (int q = 0; q < 8; ++q){
            const int k = cb + 4*q;
            const ull xjA = pack2(xjT[(k+0)*64], xjT[(k+1)*64]);
            const ull xjB = pack2(xjT[(k+2)*64], xjT[(k+3)*64]);
            const ulonglong2 x0 = xi0p[q], x1 = xi1p[q];
            accA[2*q]   = add2(accA[2*q],   add2(x0.x, xjA));
            accA[2*q+1] = add2(accA[2*q+1], add2(x0.y, xjB));
            accB[2*q]   = add2(accB[2*q],   add2(x1.x, xjA));
            accB[2*q+1] = add2(accB[2*q+1], add2(x1.y, xjB));
        }
    }

    // ---- row stats ----
    ull sA = 0, qA = 0, sB = 0, qB = 0;
#pragma unroll
    for (int q = 0; q < 16; ++q){
        sA = add2(sA, accA[q]); qA = fma2(accA[q], accA[q], qA);
        sB = add2(sB, accB[q]); qB = fma2(accB[q], accB[q], qB);
    }
    float lo, hi, sumA, sqA, sumB, sqB;
    unpack2(sA, lo, hi); sumA = lo + hi;
    unpack2(qA, lo, hi); sqA  = lo + hi;
    unpack2(sB, lo, hi); sumB = lo + hi;
    unpack2(qB, lo, hi); sqB  = lo + hi;
    sStat[((wpid*2 + 0)*2 + 0)*32 + lane] = sumA;
    sStat[((wpid*2 + 0)*2 + 1)*32 + lane] = sqA;
    sStat[((wpid*2 + 1)*2 + 0)*32 + lane] = sumB;
    sStat[((wpid*2 + 1)*2 + 1)*32 + lane] = sqB;
    __syncthreads();
    {
        const int peer = wpid ^ 1;
        sumA += sStat[((peer*2 + 0)*2 + 0)*32 + lane];
        sqA  += sStat[((peer*2 + 0)*2 + 1)*32 + lane];
        sumB += sStat[((peer*2 + 1)*2 + 0)*32 + lane];
        sqB  += sStat[((peer*2 + 1)*2 + 1)*32 + lane];
    }
    const float mA = sumA * 0.015625f;
    const float rA = rsqrtf(fmaf(-mA, mA, sqA * 0.015625f) + 1e-5f);
    const float mB = sumB * 0.015625f;
    const float rB = rsqrtf(fmaf(-mB, mB, sqB * 0.015625f) + 1e-5f);

    // ---- LN + relu + residual + s store + gate + msg product ----
    const float* xvT = g_xv + ((long)b*64)*64 + w;
    {
        const float connv = sConn[vl0*64 + w];
        const float* spT = sSg + vl0*4096 + w;
        float* gout = (MODE == 1) ? (g_s + ((long)(b*64 + vbase + vl0))*4096 + w) : (float*)0;
        float* sout = (MODE == 2 && sIdx[vl0*64 + w] >= 0)
                    ? (g_sw + ((long)(b*NSW + sIdx[vl0*64 + w]))*64) : (float*)0;
#pragma unroll
        for (int q2 = 0; q2 < 8; ++q2){
            const int k0 = cb + 4*q2;
            float a0, a1, a2, a3;
            unpack2(accA[2*q2],   a0, a1);
            unpack2(accA[2*q2+1], a2, a3);
            a0 = fmaxf((a0 - mA)*rA, 0.f); a1 = fmaxf((a1 - mA)*rA, 0.f);
            a2 = fmaxf((a2 - mA)*rA, 0.f); a3 = fmaxf((a3 - mA)*rA, 0.f);
            if (MODE != 0){
                a0 += spT[(k0+0)*64]; a1 += spT[(k0+1)*64];
                a2 += spT[(k0+2)*64]; a3 += spT[(k0+3)*64];
            }
            if (MODE == 1){
                gout[(k0+0)*64] = a0; gout[(k0+1)*64] = a1;
                gout[(k0+2)*64] = a2; gout[(k0+3)*64] = a3;
            }
            if (MODE == 2 && sout){
                sout[k0+0] = a0; sout[k0+1] = a1; sout[k0+2] = a2; sout[k0+3] = a3;
            }
            const float g0 = connv * fast_sigmoid(a0);
            const float g1 = connv * fast_sigmoid(a1);
            const float g2 = connv * fast_sigmoid(a2);
            const float g3 = connv * fast_sigmoid(a3);
            accA[2*q2]   = mul2(pack2(g0, g1), pack2(xvT[(k0+0)*64], xvT[(k0+1)*64]));
            accA[2*q2+1] = mul2(pack2(g2, g3), pack2(xvT[(k0+2)*64], xvT[(k0+3)*64]));
        }
    }
    {
        const float connv = sConn[vl1*64 + w];
        const float* spT = sSg + vl1*4096 + w;
        float* gout = (MODE == 1) ? (g_s + ((long)(b*64 + vbase + vl1))*4096 + w) : (float*)0;
        float* sout = (MODE == 2 && sIdx[vl1*64 + w] >= 0)
                    ? (g_sw + ((long)(b*NSW + sIdx[vl1*64 + w]))*64) : (float*)0;
#pragma unroll
        for (int q2 = 0; q2 < 8; ++q2){
            const int k0 = cb + 4*q2;
            float a0, a1, a2, a3;
            unpack2(accB[2*q2],   a0, a1);
            unpack2(accB[2*q2+1], a2, a3);
            a0 = fmaxf((a0 - mB)*rB, 0.f); a1 = fmaxf((a1 - mB)*rB, 0.f);
            a2 = fmaxf((a2 - mB)*rB, 0.f); a3 = fmaxf((a3 - mB)*rB, 0.f);
            if (MODE != 0){
                a0 += spT[(k0+0)*64]; a1 += spT[(k0+1)*64];
                a2 += spT[(k0+2)*64]; a3 += spT[(k0+3)*64];
            }
            if (MODE == 1){
                gout[(k0+0)*64] = a0; gout[(k0+1)*64] = a1;
                gout[(k0+2)*64] = a2; gout[(k0+3)*64] = a3;
            }
            if (MODE == 2 && sout){
                sout[k0+0] = a0; sout[k0+1] = a1; sout[k0+2] = a2; sout[k0+3] = a3;
            }
            const float g0 = connv * fast_sigmoid(a0);
            const float g1 = connv * fast_sigmoid(a1);
            const float g2 = connv * fast_sigmoid(a2);
            const float g3 = connv * fast_sigmoid(a3);
            accB[2*q2]   = mul2(pack2(g0, g1), pack2(xvT[(k0+0)*64], xvT[(k0+1)*64]));
            accB[2*q2+1] = mul2(pack2(g2, g3), pack2(xvT[(k0+2)*64], xvT[(k0+3)*64]));
        }
    }
    __syncthreads();  // done reading sSg; reuse region as msg matrix (stride 66)

    {
        float* mp0 = sMsg + vl0*4224 + w*66 + cb;
        float* mp1 = sMsg + vl1*4224 + w*66 + cb;
#pragma unroll
        for (int q = 0; q < 16; ++q){
            *(ull*)(mp0 + 2*q) = accA[q];
            *(ull*)(mp1 + 2*q) = accB[q];
        }
    }
    __syncthreads();

    // ---- msg reduce + node update ----
    {
        const int vl  = wpid >> 1;
        const int col = (wpid & 1)*32 + lane;
        const float* mpv = sMsg + vl*4224 + col;
        float msg = 0.f;
#pragma unroll 8
        for (int ww = 0; ww < 64; ++ww) msg += mpv[ww*66];
        const int vg = vbase + vl;
        const long nidx = ((long)b*64 + vg)*64 + col;
        const float tval = g_xu[nidx] + msg * g_deginv[vg];
        const float s1 = wsum(tval);
        const float s2 = wsum(tval * tval);
        if (lane == 0){
            sStat[vl*4 + (wpid & 1)*2 + 0] = s1;
            sStat[vl*4 + (wpid & 1)*2 + 1] = s2;
        }
        __syncthreads();
        const float st = sStat[vl*4 + 0] + sStat[vl*4 + 2];
        const float qt = sStat[vl*4 + 1] + sStat[vl*4 + 3];
        const float mean = st * 0.015625f;
        const float rstd = rsqrtf(fmaf(-mean, mean, qt * 0.015625f) + 1e-5f);
        float h = fmaxf((tval - mean) * rstd, 0.f);
        if (MODE != 0) h += g_x[nidx];
        g_x[nidx] = h;
    }
}

// ---------------- graph feature ----------------
__global__ void xg_kernel()
{
    const int b = blockIdx.x, k = threadIdx.x;
    float a = 0.f;
    for (int v = 0; v < VN; ++v) a += g_x[((long)b*VN + v)*HID + k];
    g_xg[b*HID + k] = a;
}

// ---------------- switch head: 32 rows/block GEMM (256 -> 256 -> 4) ----------------
__global__ void smlp_kernel(const float* __restrict__ W1, const float* __restrict__ W2,
                            const int* __restrict__ edge_S, float* __restrict__ out)
{
    __shared__ float sinT[256*36];
    __shared__ float sW2[256*4];
    __shared__ int srow[4*32];
    const int t = threadIdx.x;       // 256
    const int blk = blockIdx.x;
    if (t < 32){
        const int gid = blk*32 + t;
        if (gid < BN*NSW){
            const int b = gid / NSW, e = gid - b*NSW;
            srow[t] = b; srow[32+t] = edge_S[e]; srow[64+t] = edge_S[NSW+e]; srow[96+t] = e;
        } else srow[t] = -1;
    }
    for (int i = t; i < 1024; i += 256) sW2[i] = W2[i];
    __syncthreads();

    const int seg = t >> 6, kk = t & 63;
    for (int r = 0; r < 32; ++r){
        const int b = srow[r];
        float val = 0.f;
        if (b >= 0){
            const int si = srow[32+r], sj = srow[64+r], e = srow[96+r];
            if      (seg == 0) val = g_sw[((long)b*NSW + e)*64 + kk];
            else if (seg == 1) val = g_x[((long)b*VN + si)*HID + kk];
            else if (seg == 2) val = g_x[((long)b*VN + sj)*HID + kk];
            else               val = g_xg[b*HID + kk];
        }
        sinT[t*36 + r] = val;
    }
    __syncthreads();

    ull acc[16];
#pragma unroll
    for (int q = 0; q < 16; ++q) acc[q] = 0ull;
#pragma unroll 4
    for (int h = 0; h < 256; ++h){
        const float wv = W1[h*256 + t];
        const ull w2 = pack2(wv, wv);
        const ulonglong2* xp = (const ulonglong2*)(sinT + h*36);
#pragma unroll
        for (int q = 0; q < 8; ++q){
            const ulonglong2 xq = xp[q];
            acc[2*q]   = fma2(xq.x, w2, acc[2*q]);
            acc[2*q+1] = fma2(xq.y, w2, acc[2*q+1]);
        }
    }
    __syncthreads();
    {
        float* hd = sinT + t*36;
#pragma unroll
        for (int q = 0; q < 16; ++q){
            float a, bq; unpack2(acc[q], a, bq);
            hd[2*q]   = fmaxf(a, 0.f);
            hd[2*q+1] = fmaxf(bq, 0.f);
        }
    }
    __syncthreads();

    if (t < 128){
        const int j = t & 3, r = t >> 2;
        const int gid = blk*32 + r;
        if (gid < BN*NSW){
            float a = 0.f;
#pragma unroll 8
            for (int h = 0; h < 256; ++h) a = fmaf(sinT[h*36 + r], sW2[h*4 + j], a);
            const float sg = sigmoidf(a);
            const int b = gid / NSW, e = gid - b*NSW;
            if      (j == 0) out[b*OUTC + 2*MN + VN - NSW + e] = sg;
            else if (j == 1) out[b*OUTC + EC + e] = sg - 0.5f;
            else if (j == 2) g_vpar[b*MN + EC + e] = fmaf(0.2f, sg, 0.9f);
            else             g_vchi[b*MN + EC + e] = fmaf(0.2f, sg, 0.9f);
        }
    }
}

// ---------------- connection head: 32 rows/block GEMM (192 -> 192 -> 3) ----------------
__global__ void cmlp_kernel(const float* __restrict__ W1, const float* __restrict__ W2,
                            const int* __restrict__ edge_A, float* __restrict__ out)
{
    __shared__ float sinT[192*36];
    __shared__ float sW2[192*3];
    __shared__ int srow[3*32];
    const int t = threadIdx.x;    // 192
    const int blk = blockIdx.x;
    if (t < 32){
        const int gid = blk*32 + t;
        if (gid < BN*EC){
            const int b = gid / EC, e = gid - b*EC;
            srow[t] = b; srow[32+t] = edge_A[e]; srow[64+t] = edge_A[EC+e];
        } else srow[t] = -1;
    }
    for (int i = t; i < 576; i += 192) sW2[i] = W2[i];
    __syncthreads();

    const int seg = t >> 6, kk = t & 63;
    for (int r = 0; r < 32; ++r){
        const int b = srow[r];
        float val = 0.f;
        if (b >= 0){
            const int ai = srow[32+r], aj = srow[64+r];
            if      (seg == 0) val = g_x[((long)b*VN + ai)*HID + kk];
            else if (seg == 1) val = g_x[((long)b*VN + aj)*HID + kk];
            else               val = g_xg[b*HID + kk];
        }
        sinT[t*36 + r] = val;
    }
    __syncthreads();

    ull acc[16];
#pragma unroll
    for (int q = 0; q < 16; ++q) acc[q] = 0ull;
#pragma unroll 4
    for (int h = 0; h < 192; ++h){
        const float wv = W1[h*192 + t];
        const ull w2 = pack2(wv, wv);
        const ulonglong2* xp = (const ulonglong2*)(sinT + h*36);
#pragma unroll
        for (int q = 0; q < 8; ++q){
            const ulonglong2 xq = xp[q];
            acc[2*q]   = fma2(xq.x, w2, acc[2*q]);
            acc[2*q+1] = fma2(xq.y, w2, acc[2*q+1]);
        }
    }
    __syncthreads();
    {
        float* hd = sinT + t*36;
#pragma unroll
        for (int q = 0; q < 16; ++q){
            float a, bq; unpack2(acc[q], a, bq);
            hd[2*q]   = fmaxf(a, 0.f);
            hd[2*q+1] = fmaxf(bq, 0.f);
        }
    }
    __syncthreads();

    if (t < 96){
        const int j = t % 3, r = t / 3;
        const int gid = blk*32 + r;
        if (gid < BN*EC){
            float a = 0.f;
#pragma unroll 8
            for (int h = 0; h < 192; ++h) a = fmaf(sinT[h*36 + r], sW2[h*3 + j], a);
            const float sg = sigmoidf(a);
            const int b = gid / EC, e = gid - b*EC;
            if      (j == 0) out[b*OUTC + e] = sg - 0.5f;
            else if (j == 1) g_vpar[b*MN + e] = fmaf(0.2f, sg, 0.9f);
            else             g_vchi[b*MN + e] = fmaf(0.2f, sg, 0.9f);
        }
    }
}

// ---------------- voltage scatter + constants ----------------
__global__ void vout_kernel(float* __restrict__ out)
{
    __shared__ float vp[MN], vc[MN];
    const int b = blockIdx.x, t = threadIdx.x; // 64
    for (int i = t; i < MN; i += 64){
        vp[i] = g_vpar[b*MN + i];
        vc[i] = g_vchi[b*MN + i];
    }
    __syncthreads();
    float acc = 0.f;
    for (int m = 0; m < MN; ++m){
        acc = fmaf(vp[m], g_Wp[t*MN + m], acc);
        acc = fmaf(vc[m], g_Wc[t*MN + m], acc);
    }
    out[b*OUTC + MN + t] = (t == 0) ? 1.0f : acc;
    if (t < EC) out[b*OUTC + MN + VN + t] = 1.0f;
}

// ---------------- launch ----------------
extern "C" void kernel_launch(void* const* d_in, const int* in_sizes, int n_in,
                              void* d_out, int out_size)
{
    const float* x       = (const float*)d_in[0];
    const float* A       = (const float*)d_in[1];
    const float* S       = (const float*)d_in[2];
    const float* embed_s = (const float*)d_in[3];
    const float* p0_Ws   = (const float*)d_in[4];
    const float* p0_Wi   = (const float*)d_in[5];
    const float* p0_Wj   = (const float*)d_in[6];
    const float* p0_U    = (const float*)d_in[7];
    const float* p0_V    = (const float*)d_in[8];
    const float* pl_Ws   = (const float*)d_in[9];
    const float* pl_Wi   = (const float*)d_in[10];
    const float* pl_Wj   = (const float*)d_in[11];
    const float* pl_U    = (const float*)d_in[12];
    const float* pl_V    = (const float*)d_in[13];
    const float* smlp_W1 = (const float*)d_in[14];
    const float* smlp_W2 = (const float*)d_in[15];
    const float* cmlp_W1 = (const float*)d_in[16];
    const float* cmlp_W2 = (const float*)d_in[17];
    const float* Dinv    = (const float*)d_in[18];
    const float* Incp    = (const float*)d_in[19];
    const float* Incc    = (const float*)d_in[20];
    const int*   edge_A  = (const int*)d_in[21];
    const int*   edge_S  = (const int*)d_in[22];
    float* out = (float*)d_out;

    cudaFuncSetAttribute(layer_kernel<0>, cudaFuncAttributeMaxDynamicSharedMemorySize, LAYER_SMEM);
    cudaFuncSetAttribute(layer_kernel<1>, cudaFuncAttributeMaxDynamicSharedMemorySize, LAYER_SMEM);
    cudaFuncSetAttribute(layer_kernel<2>, cudaFuncAttributeMaxDynamicSharedMemorySize, LAYER_SMEM);

    setup_kernel<<<1, 256>>>(A, S, embed_s, p0_Ws, Dinv, Incp, Incc, edge_S);

    // layer 0 (first=True): embed lookup, NO s store
    proj_kernel<32, false, 0><<<BV/32, 256>>>(x, p0_Wi, p0_Wj, p0_U, p0_V);
    layer_kernel<0><<<BN*16, 256, LAYER_SMEM>>>(nullptr);

    // layer 1: recompute s0 in smem, write s1
    proj_kernel<64, true, 1><<<BV/32, 256>>>(nullptr, pl_Wi, pl_Wj, pl_U, pl_V);
    layer_kernel<1><<<BN*16, 256, LAYER_SMEM>>>(pl_Ws);

    // layer 2 (last): read s1, compact switch-edge store
    proj_kernel<64, true, 1><<<BV/32, 256>>>(nullptr, pl_Wi + 4096, pl_Wj + 4096,
                                             pl_U + 4096, pl_V + 4096);
    layer_kernel<2><<<BN*16, 256, LAYER_SMEM>>>(pl_Ws + 4096);

    xg_kernel<<<BN, 64>>>();
    smlp_kernel<<<(BN*NSW + 31)/32, 256>>>(smlp_W1, smlp_W2, edge_S, out);
    cmlp_kernel<<<(BN*EC + 31)/32, 192>>>(cmlp_W1, cmlp_W2, edge_A, out);
    vout_kernel<<<BN, 64>>>(out);
}

// round 14
// speedup vs baseline: 2.4746x; 1.1785x over previous
#include <cuda_runtime.h>

#define BN 200
#define VN 64
#define HID 64
#define BV (BN*VN)
#define MN 73
#define NSW 10
#define EC 63
#define OUTC 210

// ---- layer kernel smem layout (floats), 2 v per block ----
#define SM_WS    8192
#define SM_STAT  12288
#define SM_EMB   12800
#define SM_CONN  12928
#define SM_SID   13056
#define SM_IDX   13184
#define SM_NBR   13312
#define SM_MSG   13440
#define SM_TOT   13952
#define LAYER_SMEM (SM_TOT*4)

typedef unsigned long long ull;

// ---------------- device scratch ----------------
__device__ float g_s[(long long)BN*VN*VN*HID];   // h-major [b][v][h][w]; layer1 write, layer2 read
__device__ float g_sw[BN*NSW*HID];               // compact switch-edge s2 rows
__device__ float g_x[BV*HID];
__device__ float g_xi0[BV*HID];
__device__ float g_xj0[BV*HID];                  // transposed [b][k][w]
__device__ float g_xi[BV*HID];
__device__ float g_xj[BV*HID];                   // transposed [b][k][w]
__device__ float g_xu[BV*HID];
__device__ float g_xv[BV*HID];                   // transposed [b][k][w]
__device__ float g_xg[BN*HID];
__device__ float g_vpar[BN*MN];
__device__ float g_vchi[BN*MN];
__device__ float g_conn[VN*VN];
__device__ float g_deginv[VN];
__device__ float g_embp[2*HID];
__device__ float g_Wp[VN*MN];
__device__ float g_Wc[VN*MN];
__device__ int   g_Sint[VN*VN];
__device__ int   g_swidx[VN*VN];                 // (v,w) -> switch index or -1
__device__ int   g_nbrslot[VN*VN];               // (v,w) -> neighbor slot 0..3 or -1

// ---------------- f32x2 helpers ----------------
__device__ __forceinline__ ull fma2(ull a, ull b, ull c){
    ull d; asm("fma.rn.f32x2 %0, %1, %2, %3;" : "=l"(d) : "l"(a), "l"(b), "l"(c)); return d;
}
__device__ __forceinline__ ull add2(ull a, ull b){
    ull d; asm("add.rn.f32x2 %0, %1, %2;" : "=l"(d) : "l"(a), "l"(b)); return d;
}
__device__ __forceinline__ ull pack2(float lo, float hi){
    ull d; asm("mov.b64 %0, {%1, %2};" : "=l"(d) : "f"(lo), "f"(hi)); return d;
}
__device__ __forceinline__ void unpack2(ull v, float& lo, float& hi){
    asm("mov.b64 {%0, %1}, %2;" : "=f"(lo), "=f"(hi) : "l"(v));
}
__device__ __forceinline__ float sigmoidf(float x){
    return __fdividef(1.0f, 1.0f + __expf(-x));
}
__device__ __forceinline__ float fast_sigmoid(float x){
    float t; asm("tanh.approx.f32 %0, %1;" : "=f"(t) : "f"(0.5f*x));
    return fmaf(0.5f, t, 0.5f);
}
__device__ __forceinline__ float wsum(float v){
#pragma unroll
    for (int o = 16; o; o >>= 1) v += __shfl_xor_sync(0xffffffffu, v, o);
    return v;
}

// ---------------- setup ----------------
__global__ void setup_kernel(const float* __restrict__ A, const float* __restrict__ S,
                             const float* __restrict__ embed_s, const float* __restrict__ p0_Ws,
                             const float* __restrict__ Dinv,
                             const float* __restrict__ Incp, const float* __restrict__ Incc,
                             const int* __restrict__ edge_S)
{
    const int t = threadIdx.x; // 256
    for (int i = t; i < VN*VN; i += 256){
        float a = A[i] + S[i];
        g_conn[i]  = fminf(fmaxf(a, 0.f), 1.f);
        g_Sint[i]  = (int)(S[i] + 0.5f);
        g_swidx[i] = -1;
        g_nbrslot[i] = -1;
    }
    __syncthreads();
    if (t < VN){
        float s = 0.f;
        int slot = 0;
        for (int w = 0; w < VN; ++w){
            s += g_conn[t*VN + w];
            if (g_conn[t*VN + w] != 0.f && slot < 4){
                g_nbrslot[t*VN + w] = slot++;
            }
        }
        g_deginv[t] = __fdividef(1.0f, fmaxf(s, 1.0f));
    }
    if (t < 2*HID){
        int e = t >> 6, k = t & 63;
        float acc = 0.f;
        for (int h = 0; h < 32; ++h) acc = fmaf(embed_s[e*32 + h], p0_Ws[h*64 + k], acc);
        g_embp[t] = acc;
    }
    for (int i = t; i < VN*MN; i += 256){
        int n = i / MN;
        float d = Dinv[n*VN + n];
        g_Wp[i] = d * Incp[i];
        g_Wc[i] = d * Incc[i];
    }
    __syncthreads();
    if (t < NSW){
        int si = edge_S[t], sj = edge_S[NSW + t];
        g_swidx[si*VN + sj] = t;
    }
}

// ---------------- node projections: 32 rows/block ----------------
template<int IN, bool FROMX, int SLOT>
__global__ void proj_kernel(const float* __restrict__ src,
                            const float* __restrict__ Wi, const float* __restrict__ Wj,
                            const float* __restrict__ Wu, const float* __restrict__ Wv)
{
    __shared__ float sxT[IN*36];
    const int bv0 = blockIdx.x * 32;
    const int b   = bv0 >> 6;
    const int w0  = bv0 & 63;
    const int t = threadIdx.x;   // 256
    const float* s = FROMX ? (const float*)g_x : src;
    for (int i = t; i < 32*IN; i += 256){
        int r = i / IN, h = i - r*IN;
        sxT[h*36 + r] = s[(long)(bv0 + r)*IN + h];
    }
    __syncthreads();
    const int m = t >> 6, c = t & 63;
    const float* W = (m == 0) ? Wi : (m == 1) ? Wj : (m == 2) ? Wu : Wv;
    ull acc[16];
#pragma unroll
    for (int q = 0; q < 16; ++q) acc[q] = 0ull;
#pragma unroll 4
    for (int h = 0; h < IN; ++h){
        const float wv = W[h*64 + c];
        const ull w2 = pack2(wv, wv);
        const ulonglong2* xp = (const ulonglong2*)(sxT + h*36);
#pragma unroll
        for (int q2 = 0; q2 < 8; ++q2){
            const ulonglong2 xq = xp[q2];
            acc[2*q2]   = fma2(xq.x, w2, acc[2*q2]);
            acc[2*q2+1] = fma2(xq.y, w2, acc[2*q2+1]);
        }
    }
    float tmp[32];
#pragma unroll
    for (int q = 0; q < 16; ++q) unpack2(acc[q], tmp[2*q], tmp[2*q+1]);
    if (m == 0 || m == 2){
        float* dst = (m == 0) ? (SLOT == 0 ? g_xi0 : g_xi) : g_xu;
#pragma unroll
        for (int r = 0; r < 32; ++r) dst[(long)(bv0 + r)*64 + c] = tmp[r];
    } else {
        float* base = (m == 1) ? (SLOT == 0 ? g_xj0 : g_xj) : g_xv;
        float* dst = base + ((long)(b*64 + c))*64 + w0;
#pragma unroll
        for (int q = 0; q < 8; ++q)
            *(float4*)(dst + 4*q) = make_float4(tmp[4*q], tmp[4*q+1], tmp[4*q+2], tmp[4*q+3]);
    }
}

// ---------------- fused layer kernel ----------------
// 128 threads, 4 warps, 2 v's per block (4 blocks/SM).
// warp wpid: rh = wpid>>1, kh = wpid&1. lane owns row w = rh*32+lane,
// cols [kh*32, kh*32+32), for both v's (vl0=0, vl1=1).
// MODE 0: embp lookup, no s store, sparse epilogue
// MODE 1: recompute s0, GEMM, dense s1 store (streaming)
// MODE 2: load s1 (streaming), GEMM, sparse epilogue + g_sw rows
template<int MODE>
__global__ __launch_bounds__(128, 4) void layer_kernel(const float* __restrict__ Ws)
{
    extern __shared__ float sm[];
    float* sSg   = sm;            // [v][h][w]  2*4096
    float* sWs   = sm + SM_WS;
    float* sStat = sm + SM_STAT;
    float* sEmb  = sm + SM_EMB;
    float* sConn = sm + SM_CONN;
    int*   sSid  = (int*)(sm + SM_SID);
    int*   sIdx  = (int*)(sm + SM_IDX);
    int*   sNbr  = (int*)(sm + SM_NBR);
    float* sMsg  = sm + SM_MSG;   // [v][slot][k] 2*4*64

    const int b     = blockIdx.x >> 5;
    const int vbase = (blockIdx.x & 31) << 1;
    const int t = threadIdx.x;
    const int wpid = t >> 5, lane = t & 31;

    // ---- stage ----
    if (MODE == 2){
        const float4* gs4 = (const float4*)(g_s + ((long)(b*VN + vbase))*(VN*HID));
        float4* ss4 = (float4*)sSg;
        for (int i = t; i < 2048; i += 128) ss4[i] = __ldcs(gs4 + i);
    }
    if (MODE != 0){
        for (int i = t; i < 1024; i += 128)
            ((float4*)sWs)[i] = ((const float4*)Ws)[i];
    }
    {
        const int v = t >> 6, w = t & 63;   // covers 2x64
        sConn[t] = g_conn[(vbase + v)*VN + w];
        sNbr[t]  = g_nbrslot[(vbase + v)*VN + w];
        if (MODE == 0) sSid[t] = g_Sint[(vbase + v)*VN + w];
        if (MODE == 2) sIdx[t] = g_swidx[(vbase + v)*VN + w];
    }
    for (int i = t; i < 512; i += 128) sMsg[i] = 0.f;
    if (MODE != 2) sEmb[t] = g_embp[t];
    __syncthreads();

    if (MODE == 1){
        // recompute s0 = relu(LN(embp[sid] + xi0 + xj0)) into sSg (thread-local LN)
        const int v = t >> 6, w = t & 63;
        const int sid = g_Sint[(vbase + v)*VN + w];
        const float* emb = sEmb + sid*64;
        const float* xi0 = g_xi0 + ((long)b*64 + vbase + v)*64;
        const float* xj0 = g_xj0 + ((long)b*64)*64 + w;
        float* scol = sSg + v*4096 + w;
        float s1 = 0.f, s2 = 0.f;
#pragma unroll 4
        for (int h = 0; h < 64; ++h){
            const float val = emb[h] + xi0[h] + xj0[h*64];
            scol[h*64] = val;
            s1 += val; s2 = fmaf(val, val, s2);
        }
        const float mean = s1 * 0.015625f;
        const float rstd = rsqrtf(fmaf(-mean, mean, s2 * 0.015625f) + 1e-5f);
#pragma unroll 4
        for (int h = 0; h < 64; ++h)
            scol[h*64] = fmaxf((scol[h*64] - mean) * rstd, 0.f);
        __syncthreads();
    }

    const int rh = wpid >> 1, kh = wpid & 1;
    const int w  = rh*32 + lane;
    const int cb = kh*32;

    ull accA[16], accB[16];

    if (MODE == 0){
        const int id0 = sSid[w];
        const int id1 = sSid[64 + w];
        const ulonglong2* e0p = (const ulonglong2*)(sEmb + id0*64 + cb);
        const ulonglong2* e1p = (const ulonglong2*)(sEmb + id1*64 + cb);
#pragma unroll
        for (int q = 0; q < 8; ++q){
            ulonglong2 e0 = e0p[q], e1 = e1p[q];
            accA[2*q] = e0.x; accA[2*q+1] = e0.y;
            accB[2*q] = e1.x; accB[2*q+1] = e1.y;
        }
    } else {
#pragma unroll
        for (int q = 0; q < 16; ++q){ accA[q] = 0ull; accB[q] = 0ull; }
        const float* s0p = sSg + w;
        const float* s1p = sSg + 4096 + w;
#pragma unroll 4
        for (int h = 0; h < 64; ++h){
            const float s0 = s0p[h*64], s1 = s1p[h*64];
            const ull s0d = pack2(s0, s0);
            const ull s1d = pack2(s1, s1);
            const ulonglong2* wp = (const ulonglong2*)(sWs + h*64 + cb);
#pragma unroll
            for (int q = 0; q < 8; ++q){
                const ulonglong2 wv = wp[q];
                accA[2*q]   = fma2(s0d, wv.x, accA[2*q]);
                accA[2*q+1] = fma2(s0d, wv.y, accA[2*q+1]);
                accB[2*q]   = fma2(s1d, wv.x, accB[2*q]);
                accB[2*q+1] = fma2(s1d, wv.y, accB[2*q+1]);
            }
        }
    }

    // ---- add xi (broadcast) + xj (transposed, coalesced) ----
    {
        const float* xiBuf = (MODE == 0) ? g_xi0 : g_xi;
        const float* xjBuf = (MODE == 0) ? g_xj0 : g_xj;
        const ulonglong2* xi0p = (const ulonglong2*)(xiBuf + ((long)b*64 + vbase + 0)*64 + cb);
        const ulonglong2* xi1p = (const ulonglong2*)(xiBuf + ((long)b*64 + vbase + 1)*64 + cb);
        const float* xjT = xjBuf + ((long)b*64)*64 + w;
#pragma unroll
        for (int q = 0; q < 8; ++q){
            const int k = cb + 4*q;
            const ull xjA = pack2(xjT[(k+0)*64], xjT[(k+1)*64]);
            const ull xjB = pack2(xjT[(k+2)*64], xjT[(k+3)*64]);
            const ulonglong2 x0 = xi0p[q], x1 = xi1p[q];
            accA[2*q]   = add2(accA[2*q],   add2(x0.x, xjA));
            accA[2*q+1] = add2(accA[2*q+1], add2(x0.y, xjB));
            accB[2*q]   = add2(accB[2*q],   add2(x1.x, xjA));
            accB[2*q+1] = add2(accB[2*q+1], add2(x1.y, xjB));
        }
    }

    // ---- row stats (dense, in regs) ----
    ull sA = 0, qA = 0, sB = 0, qB = 0;
#pragma unroll
    for (int q = 0; q < 16; ++q){
        sA = add2(sA, accA[q]); qA = fma2(accA[q], accA[q], qA);
        sB = add2(sB, accB[q]); qB = fma2(accB[q], accB[q], qB);
    }
    float lo, hi, sumA, sqA, sumB, sqB;
    unpack2(sA, lo, hi); sumA = lo + hi;
    unpack2(qA, lo, hi); sqA  = lo + hi;
    unpack2(sB, lo, hi); sumB = lo + hi;
    unpack2(qB, lo, hi); sqB  = lo + hi;
    sStat[((wpid*2 + 0)*2 + 0)*32 + lane] = sumA;
    sStat[((wpid*2 + 0)*2 + 1)*32 + lane] = sqA;
    sStat[((wpid*2 + 1)*2 + 0)*32 + lane] = sumB;
    sStat[((wpid*2 + 1)*2 + 1)*32 + lane] = sqB;
    __syncthreads();
    {
        const int peer = wpid ^ 1;
        sumA += sStat[((peer*2 + 0)*2 + 0)*32 + lane];
        sqA  += sStat[((peer*2 + 0)*2 + 1)*32 + lane];
        sumB += sStat[((peer*2 + 1)*2 + 0)*32 + lane];
        sqB  += sStat[((peer*2 + 1)*2 + 1)*32 + lane];
    }
    const float mA = sumA * 0.015625f;
    const float rA = rsqrtf(fmaf(-mA, mA, sqA * 0.015625f) + 1e-5f);
    const float mB = sumB * 0.015625f;
    const float rB = rsqrtf(fmaf(-mB, mB, sqB * 0.015625f) + 1e-5f);

    // ---- epilogue: per-v, dense only when required; gate/msg sparse ----
    const float* xvT = g_xv + ((long)b*64)*64 + w;
#pragma unroll
    for (int vl = 0; vl < 2; ++vl){
        const ull*  acc   = (vl == 0) ? accA : accB;
        const float mean  = (vl == 0) ? mA : mB;
        const float rstd  = (vl == 0) ? rA : rB;
        const float connv = sConn[vl*64 + w];
        const int   nslot = sNbr[vl*64 + w];
        const int   swid  = (MODE == 2) ? sIdx[vl*64 + w] : -1;
        const float* spT  = sSg + vl*4096 + w;

        if (MODE == 1){
            // dense: LN + relu + residual + streaming store; gate sparse
            float* gout = g_s + ((long)(b*64 + vbase + vl))*4096 + w;
            float* mb = (nslot >= 0) ? (sMsg + vl*256 + nslot*64) : (float*)0;
#pragma unroll
            for (int q2 = 0; q2 < 8; ++q2){
                const int k0 = cb + 4*q2;
                float a0, a1, a2, a3;
                unpack2(acc[2*q2],   a0, a1);
                unpack2(acc[2*q2+1], a2, a3);
                a0 = fmaxf((a0 - mean)*rstd, 0.f) + spT[(k0+0)*64];
                a1 = fmaxf((a1 - mean)*rstd, 0.f) + spT[(k0+1)*64];
                a2 = fmaxf((a2 - mean)*rstd, 0.f) + spT[(k0+2)*64];
                a3 = fmaxf((a3 - mean)*rstd, 0.f) + spT[(k0+3)*64];
                __stcs(gout + (k0+0)*64, a0); __stcs(gout + (k0+1)*64, a1);
                __stcs(gout + (k0+2)*64, a2); __stcs(gout + (k0+3)*64, a3);
                if (mb){
                    mb[k0+0] = fast_sigmoid(a0) * xvT[(k0+0)*64];
                    mb[k0+1] = fast_sigmoid(a1) * xvT[(k0+1)*64];
                    mb[k0+2] = fast_sigmoid(a2) * xvT[(k0+2)*64];
                    mb[k0+3] = fast_sigmoid(a3) * xvT[(k0+3)*64];
                }
            }
        } else {
            // sparse finish: only gate edges / switch rows need values
            if (nslot >= 0 || swid >= 0){
                float* mb   = (nslot >= 0) ? (sMsg + vl*256 + nslot*64) : (float*)0;
                float* sout = (swid >= 0) ? (g_sw + ((long)(b*NSW + swid))*64) : (float*)0;
#pragma unroll
                for (int q2 = 0; q2 < 8; ++q2){
                    const int k0 = cb + 4*q2;
                    float a0, a1, a2, a3;
                    unpack2(acc[2*q2],   a0, a1);
                    unpack2(acc[2*q2+1], a2, a3);
                    a0 = fmaxf((a0 - mean)*rstd, 0.f);
                    a1 = fmaxf((a1 - mean)*rstd, 0.f);
                    a2 = fmaxf((a2 - mean)*rstd, 0.f);
                    a3 = fmaxf((a3 - mean)*rstd, 0.f);
                    if (MODE == 2){
                        a0 += spT[(k0+0)*64]; a1 += spT[(k0+1)*64];
                        a2 += spT[(k0+2)*64]; a3 += spT[(k0+3)*64];
                    }
                    if (sout){
                        sout[k0+0] = a0; sout[k0+1] = a1;
                        sout[k0+2] = a2; sout[k0+3] = a3;
                    }
                    if (mb){
                        mb[k0+0] = fast_sigmoid(a0) * xvT[(k0+0)*64];
                        mb[k0+1] = fast_sigmoid(a1) * xvT[(k0+1)*64];
                        mb[k0+2] = fast_sigmoid(a2) * xvT[(k0+2)*64];
                        mb[k0+3] = fast_sigmoid(a3) * xvT[(k0+3)*64];
                    }
                }
            }
        }
    }
    __syncthreads();

    // ---- msg reduce (4 neighbor slots) + node update ----
    {
        const int vl  = wpid >> 1;
        const int col = (wpid & 1)*32 + lane;
        const float* mpv = sMsg + vl*256 + col;
        const float msg = (mpv[0] + mpv[64]) + (mpv[128] + mpv[192]);
        const int vg = vbase + vl;
        const long nidx = ((long)b*64 + vg)*64 + col;
        const float tval = g_xu[nidx] + msg * g_deginv[vg];
        const float s1 = wsum(tval);
        const float s2 = wsum(tval * tval);
        if (lane == 0){
            sStat[vl*4 + (wpid & 1)*2 + 0] = s1;
            sStat[vl*4 + (wpid & 1)*2 + 1] = s2;
        }
        __syncthreads();
        const float st = sStat[vl*4 + 0] + sStat[vl*4 + 2];
        const float qt = sStat[vl*4 + 1] + sStat[vl*4 + 3];
        const float mean = st * 0.015625f;
        const float rstd = rsqrtf(fmaf(-mean, mean, qt * 0.015625f) + 1e-5f);
        float h = fmaxf((tval - mean) * rstd, 0.f);
        if (MODE != 0) h += g_x[nidx];
        g_x[nidx] = h;
    }
}

// ---------------- graph feature ----------------
__global__ void xg_kernel()
{
    const int b = blockIdx.x, k = threadIdx.x;
    float a = 0.f;
    for (int v = 0; v < VN; ++v) a += g_x[((long)b*VN + v)*HID + k];
    g_xg[b*HID + k] = a;
}

// ---------------- switch head: 32 rows/block GEMM (256 -> 256 -> 4) ----------------
__global__ void smlp_kernel(const float* __restrict__ W1, const float* __restrict__ W2,
                            const int* __restrict__ edge_S, float* __restrict__ out)
{
    __shared__ float sinT[256*36];
    __shared__ float sW2[256*4];
    __shared__ int srow[4*32];
    const int t = threadIdx.x;       // 256
    const int blk = blockIdx.x;
    if (t < 32){
        const int gid = blk*32 + t;
        if (gid < BN*NSW){
            const int b = gid / NSW, e = gid - b*NSW;
            srow[t] = b; srow[32+t] = edge_S[e]; srow[64+t] = edge_S[NSW+e]; srow[96+t] = e;
        } else srow[t] = -1;
    }
    for (int i = t; i < 1024; i += 256) sW2[i] = W2[i];
    __syncthreads();

    const int seg = t >> 6, kk = t & 63;
    for (int r = 0; r < 32; ++r){
        const int b = srow[r];
        float val = 0.f;
        if (b >= 0){
            const int si = srow[32+r], sj = srow[64+r], e = srow[96+r];
            if      (seg == 0) val = g_sw[((long)b*NSW + e)*64 + kk];
            else if (seg == 1) val = g_x[((long)b*VN + si)*HID + kk];
            else if (seg == 2) val = g_x[((long)b*VN + sj)*HID + kk];
            else               val = g_xg[b*HID + kk];
        }
        sinT[t*36 + r] = val;
    }
    __syncthreads();

    ull acc[16];
#pragma unroll
    for (int q = 0; q < 16; ++q) acc[q] = 0ull;
#pragma unroll 4
    for (int h = 0; h < 256; ++h){
        const float wv = W1[h*256 + t];
        const ull w2 = pack2(wv, wv);
        const ulonglong2* xp = (const ulonglong2*)(sinT + h*36);
#pragma unroll
        for (int q = 0; q < 8; ++q){
            const ulonglong2 xq = xp[q];
            acc[2*q]   = fma2(xq.x, w2, acc[2*q]);
            acc[2*q+1] = fma2(xq.y, w2, acc[2*q+1]);
        }
    }
    __syncthreads();
    {
        float* hd = sinT + t*36;
#pragma unroll
        for (int q = 0; q < 16; ++q){
            float a, bq; unpack2(acc[q], a, bq);
            hd[2*q]   = fmaxf(a, 0.f);
            hd[2*q+1] = fmaxf(bq, 0.f);
        }
    }
    __syncthreads();

    if (t < 128){
        const int j = t & 3, r = t >> 2;
        const int gid = blk*32 + r;
        if (gid < BN*NSW){
            float a = 0.f;
#pragma unroll 8
            for (int h = 0; h < 256; ++h) a = fmaf(sinT[h*36 + r], sW2[h*4 + j], a);
            const float sg = sigmoidf(a);
            const int b = gid / NSW, e = gid - b*NSW;
            if      (j == 0) out[b*OUTC + 2*MN + VN - NSW + e] = sg;
            else if (j == 1) out[b*OUTC + EC + e] = sg - 0.5f;
            else if (j == 2) g_vpar[b*MN + EC + e] = fmaf(0.2f, sg, 0.9f);
            else             g_vchi[b*MN + EC + e] = fmaf(0.2f, sg, 0.9f);
        }
    }
}

// ---------------- connection head: 32 rows/block GEMM (192 -> 192 -> 3) ----------------
__global__ void cmlp_kernel(const float* __restrict__ W1, const float* __restrict__ W2,
                            const int* __restrict__ edge_A, float* __restrict__ out)
{
    __shared__ float sinT[192*36];
    __shared__ float sW2[192*3];
    __shared__ int srow[3*32];
    const int t = threadIdx.x;    // 192
    const int blk = blockIdx.x;
    if (t < 32){
        const int gid = blk*32 + t;
        if (gid < BN*EC){
            const int b = gid / EC, e = gid - b*EC;
            srow[t] = b; srow[32+t] = edge_A[e]; srow[64+t] = edge_A[EC+e];
        } else srow[t] = -1;
    }
    for (int i = t; i < 576; i += 192) sW2[i] = W2[i];
    __syncthreads();

    const int seg = t >> 6, kk = t & 63;
    for (int r = 0; r < 32; ++r){
        const int b = srow[r];
        float val = 0.f;
        if (b >= 0){
            const int ai = srow[32+r], aj = srow[64+r];
            if      (seg == 0) val = g_x[((long)b*VN + ai)*HID + kk];
            else if (seg == 1) val = g_x[((long)b*VN + aj)*HID + kk];
            else               val = g_xg[b*HID + kk];
        }
        sinT[t*36 + r] = val;
    }
    __syncthreads();

    ull acc[16];
#pragma unroll
    for (int q = 0; q < 16; ++q) acc[q] = 0ull;
#pragma unroll 4
    for (int h = 0; h < 192; ++h){
        const float wv = W1[h*192 + t];
        const ull w2 = pack2(wv, wv);
        const ulonglong2* xp = (const ulonglong2*)(sinT + h*36);
#pragma unroll
        for (int q = 0; q < 8; ++q){
            const ulonglong2 xq = xp[q];
            acc[2*q]   = fma2(xq.x, w2, acc[2*q]);
            acc[2*q+1] = fma2(xq.y, w2, acc[2*q+1]);
        }
    }
    __syncthreads();
    {
        float* hd = sinT + t*36;
#pragma unroll
        for (int q = 0; q < 16; ++q){
            float a, bq; unpack2(acc[q], a, bq);
            hd[2*q]   = fmaxf(a, 0.f);
            hd[2*q+1] = fmaxf(bq, 0.f);
        }
    }
    __syncthreads();

    if (t < 96){
        const int j = t % 3, r = t / 3;
        const int gid = blk*32 + r;
        if (gid < BN*EC){
            float a = 0.f;
#pragma unroll 8
            for (int h = 0; h < 192; ++h) a = fmaf(sinT[h*36 + r], sW2[h*3 + j], a);
            const float sg = sigmoidf(a);
            const int b = gid / EC, e = gid - b*EC;
            if      (j == 0) out[b*OUTC + e] = sg - 0.5f;
            else if (j == 1) g_vpar[b*MN + e] = fmaf(0.2f, sg, 0.9f);
            else             g_vchi[b*MN + e] = fmaf(0.2f, sg, 0.9f);
        }
    }
}

// ---------------- voltage scatter + constants ----------------
__global__ void vout_kernel(float* __restrict__ out)
{
    __shared__ float vp[MN], vc[MN];
    const int b = blockIdx.x, t = threadIdx.x; // 64
    for (int i = t; i < MN; i += 64){
        vp[i] = g_vpar[b*MN + i];
        vc[i] = g_vchi[b*MN + i];
    }
    __syncthreads();
    float acc = 0.f;
    for (int m = 0; m < MN; ++m){
        acc = fmaf(vp[m], g_Wp[t*MN + m], acc);
        acc = fmaf(vc[m], g_Wc[t*MN + m], acc);
    }
    out[b*OUTC + MN + t] = (t == 0) ? 1.0f : acc;
    if (t < EC) out[b*OUTC + MN + VN + t] = 1.0f;
}

// ---------------- launch ----------------
extern "C" void kernel_launch(void* const* d_in, const int* in_sizes, int n_in,
                              void* d_out, int out_size)
{
    const float* x       = (const float*)d_in[0];
    const float* A       = (const float*)d_in[1];
    const float* S       = (const float*)d_in[2];
    const float* embed_s = (const float*)d_in[3];
    const float* p0_Ws   = (const float*)d_in[4];
    const float* p0_Wi   = (const float*)d_in[5];
    const float* p0_Wj   = (const float*)d_in[6];
    const float* p0_U    = (const float*)d_in[7];
    const float* p0_V    = (const float*)d_in[8];
    const float* pl_Ws   = (const float*)d_in[9];
    const float* pl_Wi   = (const float*)d_in[10];
    const float* pl_Wj   = (const float*)d_in[11];
    const float* pl_U    = (const float*)d_in[12];
    const float* pl_V    = (const float*)d_in[13];
    const float* smlp_W1 = (const float*)d_in[14];
    const float* smlp_W2 = (const float*)d_in[15];
    const float* cmlp_W1 = (const float*)d_in[16];
    const float* cmlp_W2 = (const float*)d_in[17];
    const float* Dinv    = (const float*)d_in[18];
    const float* Incp    = (const float*)d_in[19];
    const float* Incc    = (const float*)d_in[20];
    const int*   edge_A  = (const int*)d_in[21];
    const int*   edge_S  = (const int*)d_in[22];
    float* out = (float*)d_out;

    cudaFuncSetAttribute(layer_kernel<0>, cudaFuncAttributeMaxDynamicSharedMemorySize, LAYER_SMEM);
    cudaFuncSetAttribute(layer_kernel<1>, cudaFuncAttributeMaxDynamicSharedMemorySize, LAYER_SMEM);
    cudaFuncSetAttribute(layer_kernel<2>, cudaFuncAttributeMaxDynamicSharedMemorySize, LAYER_SMEM);

    setup_kernel<<<1, 256>>>(A, S, embed_s, p0_Ws, Dinv, Incp, Incc, edge_S);

    // layer 0 (first=True): embed lookup, no s store, sparse epilogue
    proj_kernel<32, false, 0><<<BV/32, 256>>>(x, p0_Wi, p0_Wj, p0_U, p0_V);
    layer_kernel<0><<<BN*32, 128, LAYER_SMEM>>>(nullptr);

    // layer 1: recompute s0 in smem, write s1 (streaming)
    proj_kernel<64, true, 1><<<BV/32, 256>>>(nullptr, pl_Wi, pl_Wj, pl_U, pl_V);
    layer_kernel<1><<<BN*32, 128, LAYER_SMEM>>>(pl_Ws);

    // layer 2 (last): read s1 (streaming), sparse epilogue + compact switch rows
    proj_kernel<64, true, 1><<<BV/32, 256>>>(nullptr, pl_Wi + 4096, pl_Wj + 4096,
                                             pl_U + 4096, pl_V + 4096);
    layer_kernel<2><<<BN*32, 128, LAYER_SMEM>>>(pl_Ws + 4096);

    xg_kernel<<<BN, 64>>>();
    smlp_kernel<<<(BN*NSW + 31)/32, 256>>>(smlp_W1, smlp_W2, edge_S, out);
    cmlp_kernel<<<(BN*EC + 31)/32, 192>>>(cmlp_W1, cmlp_W2, edge_A, out);
    vout_kernel<<<BN, 64>>>(out);
}

// round 16
// speedup vs baseline: 6.8951x; 2.7864x over previous
#include <cuda_runtime.h>

#define BN 200
#define VN 64
#define HID 64
#define BV (BN*VN)
#define MN 73
#define NSW 10
#define EC 63
#define OUTC 210
#define NEP 256            // padded directed edges per graph (4 slots x 64 nodes)

typedef unsigned long long ull;

// ---------------- device scratch ----------------
__device__ float g_es[(long)BN*NEP*HID];   // edge state rows (padded list), 13MB
__device__ float g_msg[(long)BN*NEP*HID];  // per-edge msg contributions, 13MB
__device__ float g_x[BV*HID];
__device__ float g_xi[BV*HID];
__device__ float g_xj[BV*HID];
__device__ float g_xu[BV*HID];
__device__ float g_xv[BV*HID];
__device__ float g_xg[BN*HID];
__device__ float g_vpar[BN*MN];
__device__ float g_vchi[BN*MN];
__device__ float g_deginv[VN];
__device__ float g_embp[2*HID];
__device__ float g_Wp[VN*MN];
__device__ float g_Wc[VN*MN];
__device__ int   g_ew[NEP];       // edge -> target node w, or -1 inactive
__device__ float g_econn[NEP];    // conn value at edge
__device__ int   g_esint[NEP];    // S (0/1) at edge, for layer0 embed
__device__ int   g_swedge[NSW];   // switch idx -> padded edge idx

// ---------------- f32x2 helpers ----------------
__device__ __forceinline__ ull fma2(ull a, ull b, ull c){
    ull d; asm("fma.rn.f32x2 %0, %1, %2, %3;" : "=l"(d) : "l"(a), "l"(b), "l"(c)); return d;
}
__device__ __forceinline__ ull add2(ull a, ull b){
    ull d; asm("add.rn.f32x2 %0, %1, %2;" : "=l"(d) : "l"(a), "l"(b)); return d;
}
__device__ __forceinline__ ull mul2(ull a, ull b){
    ull d; asm("mul.rn.f32x2 %0, %1, %2;" : "=l"(d) : "l"(a), "l"(b)); return d;
}
__device__ __forceinline__ ull pack2(float lo, float hi){
    ull d; asm("mov.b64 %0, {%1, %2};" : "=l"(d) : "f"(lo), "f"(hi)); return d;
}
__device__ __forceinline__ void unpack2(ull v, float& lo, float& hi){
    asm("mov.b64 {%0, %1}, %2;" : "=f"(lo), "=f"(hi) : "l"(v));
}
__device__ __forceinline__ float sigmoidf(float x){
    return __fdividef(1.0f, 1.0f + __expf(-x));
}
__device__ __forceinline__ float fast_sigmoid(float x){
    float t; asm("tanh.approx.f32 %0, %1;" : "=f"(t) : "f"(0.5f*x));
    return fmaf(0.5f, t, 0.5f);
}
__device__ __forceinline__ float wsum(float v){
#pragma unroll
    for (int o = 16; o; o >>= 1) v += __shfl_xor_sync(0xffffffffu, v, o);
    return v;
}

// ---------------- setup: edge list + constants ----------------
__global__ void setup_kernel(const float* __restrict__ A, const float* __restrict__ S,
                             const float* __restrict__ embed_s, const float* __restrict__ p0_Ws,
                             const float* __restrict__ Dinv,
                             const float* __restrict__ Incp, const float* __restrict__ Incc,
                             const int* __restrict__ edge_S)
{
    __shared__ float sConn[VN*VN];
    __shared__ int   sSint[VN*VN];
    const int t = threadIdx.x; // 256
    for (int i = t; i < VN*VN; i += 256){
        float a = A[i] + S[i];
        sConn[i] = fminf(fmaxf(a, 0.f), 1.f);
        sSint[i] = (int)(S[i] + 0.5f);
    }
    if (t < NEP) g_ew[t] = -1;
    __syncthreads();
    if (t < VN){
        float s = 0.f;
        int slot = 0;
        for (int w = 0; w < VN; ++w){
            const float c = sConn[t*VN + w];
            s += c;
            if (c != 0.f && slot < 4){
                g_ew[t*4 + slot]    = w;
                g_econn[t*4 + slot] = c;
                g_esint[t*4 + slot] = sSint[t*VN + w];
                ++slot;
            }
        }
        g_deginv[t] = __fdividef(1.0f, fmaxf(s, 1.0f));
    }
    if (t < 2*HID){
        int e = t >> 6, k = t & 63;
        float acc = 0.f;
        for (int h = 0; h < 32; ++h) acc = fmaf(embed_s[e*32 + h], p0_Ws[h*64 + k], acc);
        g_embp[t] = acc;
    }
    for (int i = t; i < VN*MN; i += 256){
        int n = i / MN;
        float d = Dinv[n*VN + n];
        g_Wp[i] = d * Incp[i];
        g_Wc[i] = d * Incc[i];
    }
    __syncthreads();
    if (t < NSW){
        const int si = edge_S[t], sj = edge_S[NSW + t];
        int ep = -1;
#pragma unroll
        for (int s = 0; s < 4; ++s)
            if (g_ew[si*4 + s] == sj) ep = si*4 + s;
        g_swedge[t] = ep;
    }
}

// ---------------- node projections: 16 rows/block, all outputs row-major ----------------
template<int IN, bool FROMX>
__global__ void proj_kernel(const float* __restrict__ src,
                            const float* __restrict__ Wi, const float* __restrict__ Wj,
                            const float* __restrict__ Wu, const float* __restrict__ Wv)
{
    __shared__ float sxT[IN*20];  // [h]*20 + r
    const int bv0 = blockIdx.x * 16;
    const int t = threadIdx.x;   // 256
    const float* s = FROMX ? (const float*)g_x : src;
    for (int i = t; i < 16*IN; i += 256){
        int r = i / IN, h = i - r*IN;
        sxT[h*20 + r] = s[(long)(bv0 + r)*IN + h];
    }
    __syncthreads();
    const int m = t >> 6, c = t & 63;
    const float* W = (m == 0) ? Wi : (m == 1) ? Wj : (m == 2) ? Wu : Wv;
    ull acc[8];
#pragma unroll
    for (int q = 0; q < 8; ++q) acc[q] = 0ull;
#pragma unroll 8
    for (int h = 0; h < IN; ++h){
        const float wv = W[h*64 + c];
        const ull w2 = pack2(wv, wv);
        const ulonglong2* xp = (const ulonglong2*)(sxT + h*20);
#pragma unroll
        for (int q2 = 0; q2 < 4; ++q2){
            const ulonglong2 xq = xp[q2];
            acc[2*q2]   = fma2(xq.x, w2, acc[2*q2]);
            acc[2*q2+1] = fma2(xq.y, w2, acc[2*q2+1]);
        }
    }
    float tmp[16];
#pragma unroll
    for (int q = 0; q < 8; ++q) unpack2(acc[q], tmp[2*q], tmp[2*q+1]);
    float* dst = (m == 0) ? g_xi : (m == 1) ? g_xj : (m == 2) ? g_xu : g_xv;
#pragma unroll
    for (int r = 0; r < 16; ++r) dst[(long)(bv0 + r)*64 + c] = tmp[r];
}

// ---------------- sparse edge kernel: one warp per padded edge ----------------
// FIRST=1: s_in = embp[S], no residual. FIRST=0: row GEMM s@Ws + residual.
template<int FIRST>
__global__ __launch_bounds__(256) void edge_kernel(const float* __restrict__ Ws)
{
    __shared__ float sWs[4096];
    __shared__ float sS[8][66];
    const int b    = blockIdx.x >> 5;
    const int wpid = threadIdx.x >> 5;
    const int lane = threadIdx.x & 31;
    const int ep   = ((blockIdx.x & 31) << 3) + wpid;

    if (!FIRST){
        for (int i = threadIdx.x; i < 1024; i += 256)
            ((float4*)sWs)[i] = ((const float4*)Ws)[i];
        __syncthreads();
    }

    const int w = g_ew[ep];
    const long erow = ((long)b*NEP + ep)*64;
    if (w < 0){
        // inactive slot: keep msg row zero for the node reduction
        ((float2*)(g_msg + erow))[lane] = make_float2(0.f, 0.f);
        return;
    }
    const int v = ep >> 2;

    ull e2;
    float sp0 = 0.f, sp1 = 0.f;
    if (FIRST){
        e2 = ((const ull*)(g_embp + g_esint[ep]*64))[lane];
    } else {
        const float2 sr = ((const float2*)(g_es + erow))[lane];
        sp0 = sr.x; sp1 = sr.y;
        float* myS = sS[wpid];
        myS[2*lane]   = sr.x;
        myS[2*lane+1] = sr.y;
        __syncwarp();
        ull acc = 0ull;
#pragma unroll 8
        for (int h = 0; h < 64; ++h){
            const float sv = myS[h];
            acc = fma2(pack2(sv, sv), ((const ull*)(sWs + h*64))[lane], acc);
        }
        e2 = acc;
    }

    const long nb = ((long)b*64 + v)*64;
    const long wb = ((long)b*64 + w)*64;
    e2 = add2(e2, add2(((const ull*)(g_xi + nb))[lane],
                       ((const ull*)(g_xj + wb))[lane]));
    float a0, a1; unpack2(e2, a0, a1);
    const float s1 = wsum(a0 + a1);
    const float s2 = wsum(fmaf(a0, a0, a1*a1));
    const float mean = s1 * 0.015625f;
    const float rstd = rsqrtf(fmaf(-mean, mean, s2 * 0.015625f) + 1e-5f);
    a0 = fmaxf((a0 - mean)*rstd, 0.f) + sp0;
    a1 = fmaxf((a1 - mean)*rstd, 0.f) + sp1;
    ((float2*)(g_es + erow))[lane] = make_float2(a0, a1);

    const float c = g_econn[ep];
    const ull m2 = mul2(pack2(c*fast_sigmoid(a0), c*fast_sigmoid(a1)),
                        ((const ull*)(g_xv + wb))[lane]);
    *((ull*)(g_msg + erow) + lane) = m2;
}

// ---------------- node update: one warp per node ----------------
template<int FIRST>
__global__ __launch_bounds__(256) void node_kernel()
{
    const int b    = blockIdx.x >> 3;
    const int v    = ((blockIdx.x & 7) << 3) + (threadIdx.x >> 5);
    const int lane = threadIdx.x & 31;
    const long mbase = ((long)b*NEP + v*4)*64;
    const ull* mp = (const ull*)(g_msg + mbase);
    const ull m = add2(add2(mp[lane], mp[32 + lane]),
                       add2(mp[64 + lane], mp[96 + lane]));
    const long nb = ((long)b*64 + v)*64;
    const float d = g_deginv[v];
    const ull tv = fma2(m, pack2(d, d), ((const ull*)(g_xu + nb))[lane]);
    float t0, t1; unpack2(tv, t0, t1);
    const float s1 = wsum(t0 + t1);
    const float s2 = wsum(fmaf(t0, t0, t1*t1));
    const float mean = s1 * 0.015625f;
    const float rstd = rsqrtf(fmaf(-mean, mean, s2 * 0.015625f) + 1e-5f);
    float h0 = fmaxf((t0 - mean)*rstd, 0.f);
    float h1 = fmaxf((t1 - mean)*rstd, 0.f);
    if (!FIRST){
        const float2 xp = ((const float2*)(g_x + nb))[lane];
        h0 += xp.x; h1 += xp.y;
    }
    ((float2*)(g_x + nb))[lane] = make_float2(h0, h1);
}

// ---------------- graph feature ----------------
__global__ void xg_kernel()
{
    const int b = blockIdx.x, k = threadIdx.x;
    float a = 0.f;
    for (int v = 0; v < VN; ++v) a += g_x[((long)b*VN + v)*HID + k];
    g_xg[b*HID + k] = a;
}

// ---------------- switch head: 32 rows/block GEMM (256 -> 256 -> 4) ----------------
__global__ void smlp_kernel(const float* __restrict__ W1, const float* __restrict__ W2,
                            const int* __restrict__ edge_S, float* __restrict__ out)
{
    __shared__ float sinT[256*36];
    __shared__ float sW2[256*4];
    __shared__ int srow[4*32];
    const int t = threadIdx.x;       // 256
    const int blk = blockIdx.x;
    if (t < 32){
        const int gid = blk*32 + t;
        if (gid < BN*NSW){
            const int b = gid / NSW, e = gid - b*NSW;
            srow[t] = b; srow[32+t] = edge_S[e]; srow[64+t] = edge_S[NSW+e]; srow[96+t] = g_swedge[e];
        } else srow[t] = -1;
    }
    for (int i = t; i < 1024; i += 256) sW2[i] = W2[i];
    __syncthreads();

    const int seg = t >> 6, kk = t & 63;
    for (int r = 0; r < 32; ++r){
        const int b = srow[r];
        float val = 0.f;
        if (b >= 0){
            const int si = srow[32+r], sj = srow[64+r], ep = srow[96+r];
            if      (seg == 0) val = g_es[((long)b*NEP + ep)*64 + kk];
            else if (seg == 1) val = g_x[((long)b*VN + si)*HID + kk];
            else if (seg == 2) val = g_x[((long)b*VN + sj)*HID + kk];
            else               val = g_xg[b*HID + kk];
        }
        sinT[t*36 + r] = val;
    }
    __syncthreads();

    ull acc[16];
#pragma unroll
    for (int q = 0; q < 16; ++q) acc[q] = 0ull;
#pragma unroll 4
    for (int h = 0; h < 256; ++h){
        const float wv = W1[h*256 + t];
        const ull w2 = pack2(wv, wv);
        const ulonglong2* xp = (const ulonglong2*)(sinT + h*36);
#pragma unroll
        for (int q = 0; q < 8; ++q){
            const ulonglong2 xq = xp[q];
            acc[2*q]   = fma2(xq.x, w2, acc[2*q]);
            acc[2*q+1] = fma2(xq.y, w2, acc[2*q+1]);
        }
    }
    __syncthreads();
    {
        float* hd = sinT + t*36;
#pragma unroll
        for (int q = 0; q < 16; ++q){
            float a, bq; unpack2(acc[q], a, bq);
            hd[2*q]   = fmaxf(a, 0.f);
            hd[2*q+1] = fmaxf(bq, 0.f);
        }
    }
    __syncthreads();

    if (t < 128){
        const int j = t & 3, r = t >> 2;
        const int gid = blk*32 + r;
        if (gid < BN*NSW){
            float a = 0.f;
#pragma unroll 8
            for (int h = 0; h < 256; ++h) a = fmaf(sinT[h*36 + r], sW2[h*4 + j], a);
            const float sg = sigmoidf(a);
            const int b = gid / NSW, e = gid - b*NSW;
            if      (j == 0) out[b*OUTC + 2*MN + VN - NSW + e] = sg;
            else if (j == 1) out[b*OUTC + EC + e] = sg - 0.5f;
            else if (j == 2) g_vpar[b*MN + EC + e] = fmaf(0.2f, sg, 0.9f);
            else             g_vchi[b*MN + EC + e] = fmaf(0.2f, sg, 0.9f);
        }
    }
}

// ---------------- connection head: 32 rows/block GEMM (192 -> 192 -> 3) ----------------
__global__ void cmlp_kernel(const float* __restrict__ W1, const float* __restrict__ W2,
                            const int* __restrict__ edge_A, float* __restrict__ out)
{
    __shared__ float sinT[192*36];
    __shared__ float sW2[192*3];
    __shared__ int srow[3*32];
    const int t = threadIdx.x;    // 192
    const int blk = blockIdx.x;
    if (t < 32){
        const int gid = blk*32 + t;
        if (gid < BN*EC){
            const int b = gid / EC, e = gid - b*EC;
            srow[t] = b; srow[32+t] = edge_A[e]; srow[64+t] = edge_A[EC+e];
        } else srow[t] = -1;
    }
    for (int i = t; i < 576; i += 192) sW2[i] = W2[i];
    __syncthreads();

    const int seg = t >> 6, kk = t & 63;
    for (int r = 0; r < 32; ++r){
        const int b = srow[r];
        float val = 0.f;
        if (b >= 0){
            const int ai = srow[32+r], aj = srow[64+r];
            if      (seg == 0) val = g_x[((long)b*VN + ai)*HID + kk];
            else if (seg == 1) val = g_x[((long)b*VN + aj)*HID + kk];
            else               val = g_xg[b*HID + kk];
        }
        sinT[t*36 + r] = val;
    }
    __syncthreads();

    ull acc[16];
#pragma unroll
    for (int q = 0; q < 16; ++q) acc[q] = 0ull;
#pragma unroll 4
    for (int h = 0; h < 192; ++h){
        const float wv = W1[h*192 + t];
        const ull w2 = pack2(wv, wv);
        const ulonglong2* xp = (const ulonglong2*)(sinT + h*36);
#pragma unroll
        for (int q = 0; q < 8; ++q){
            const ulonglong2 xq = xp[q];
            acc[2*q]   = fma2(xq.x, w2, acc[2*q]);
            acc[2*q+1] = fma2(xq.y, w2, acc[2*q+1]);
        }
    }
    __syncthreads();
    {
        float* hd = sinT + t*36;
#pragma unroll
        for (int q = 0; q < 16; ++q){
            float a, bq; unpack2(acc[q], a, bq);
            hd[2*q]   = fmaxf(a, 0.f);
            hd[2*q+1] = fmaxf(bq, 0.f);
        }
    }
    __syncthreads();

    if (t < 96){
        const int j = t % 3, r = t / 3;
        const int gid = blk*32 + r;
        if (gid < BN*EC){
            float a = 0.f;
#pragma unroll 8
            for (int h = 0; h < 192; ++h) a = fmaf(sinT[h*36 + r], sW2[h*3 + j], a);
            const float sg = sigmoidf(a);
            const int b = gid / EC, e = gid - b*EC;
            if      (j == 0) out[b*OUTC + e] = sg - 0.5f;
            else if (j == 1) g_vpar[b*MN + e] = fmaf(0.2f, sg, 0.9f);
            else             g_vchi[b*MN + e] = fmaf(0.2f, sg, 0.9f);
        }
    }
}

// ---------------- voltage scatter + constants ----------------
__global__ void vout_kernel(float* __restrict__ out)
{
    __shared__ float vp[MN], vc[MN];
    const int b = blockIdx.x, t = threadIdx.x; // 64
    for (int i = t; i < MN; i += 64){
        vp[i] = g_vpar[b*MN + i];
        vc[i] = g_vchi[b*MN + i];
    }
    __syncthreads();
    float acc = 0.f;
    for (int m = 0; m < MN; ++m){
        acc = fmaf(vp[m], g_Wp[t*MN + m], acc);
        acc = fmaf(vc[m], g_Wc[t*MN + m], acc);
    }
    out[b*OUTC + MN + t] = (t == 0) ? 1.0f : acc;
    if (t < EC) out[b*OUTC + MN + VN + t] = 1.0f;
}

// ---------------- launch ----------------
extern "C" void kernel_launch(void* const* d_in, const int* in_sizes, int n_in,
                              void* d_out, int out_size)
{
    const float* x       = (const float*)d_in[0];
    const float* A       = (const float*)d_in[1];
    const float* S       = (const float*)d_in[2];
    const float* embed_s = (const float*)d_in[3];
    const float* p0_Ws   = (const float*)d_in[4];
    const float* p0_Wi   = (const float*)d_in[5];
    const float* p0_Wj   = (const float*)d_in[6];
    const float* p0_U    = (const float*)d_in[7];
    const float* p0_V    = (const float*)d_in[8];
    const float* pl_Ws   = (const float*)d_in[9];
    const float* pl_Wi   = (const float*)d_in[10];
    const float* pl_Wj   = (const float*)d_in[11];
    const float* pl_U    = (const float*)d_in[12];
    const float* pl_V    = (const float*)d_in[13];
    const float* smlp_W1 = (const float*)d_in[14];
    const float* smlp_W2 = (const float*)d_in[15];
    const float* cmlp_W1 = (const float*)d_in[16];
    const float* cmlp_W2 = (const float*)d_in[17];
    const float* Dinv    = (const float*)d_in[18];
    const float* Incp    = (const float*)d_in[19];
    const float* Incc    = (const float*)d_in[20];
    const int*   edge_A  = (const int*)d_in[21];
    const int*   edge_S  = (const int*)d_in[22];
    float* out = (float*)d_out;

    setup_kernel<<<1, 256>>>(A, S, embed_s, p0_Ws, Dinv, Incp, Incc, edge_S);

    // layer 0 (first=True)
    proj_kernel<32, false><<<BV/16, 256>>>(x, p0_Wi, p0_Wj, p0_U, p0_V);
    edge_kernel<1><<<BN*32, 256>>>(nullptr);
    node_kernel<1><<<BN*8, 256>>>();

    // layer 1
    proj_kernel<64, true><<<BV/16, 256>>>(nullptr, pl_Wi, pl_Wj, pl_U, pl_V);
    edge_kernel<0><<<BN*32, 256>>>(pl_Ws);
    node_kernel<0><<<BN*8, 256>>>();

    // layer 2
    proj_kernel<64, true><<<BV/16, 256>>>(nullptr, pl_Wi + 4096, pl_Wj + 4096,
                                          pl_U + 4096, pl_V + 4096);
    edge_kernel<0><<<BN*32, 256>>>(pl_Ws + 4096);
    node_kernel<0><<<BN*8, 256>>>();

    xg_kernel<<<BN, 64>>>();
    smlp_kernel<<<(BN*NSW + 31)/32, 256>>>(smlp_W1, smlp_W2, edge_S, out);
    cmlp_kernel<<<(BN*EC + 31)/32, 192>>>(cmlp_W1, cmlp_W2, edge_A, out);
    vout_kernel<<<BN, 64>>>(out);
}